// round 1
// baseline (speedup 1.0000x reference)
#include <cuda_runtime.h>
#include <cstdio>

#define DD     12
#define VOLPB  1728
#define BATCH  512
#define NPTS   442368          // 512 * 864
#define NVOX   884736          // 512 * 1728
#define BM     128
#define NBLK   3456            // NPTS / BM
#define INVN   (1.0f/442368.0f)
#define BN_EPS 1e-5f

// ---------------- scratch (device globals; no allocations allowed) ----------
__device__ int   g_map[NVOX];
__device__ int   g_nbr[27 * NPTS];
__device__ float g_feat[(size_t)NPTS * 128];
__device__ float g_conv[(size_t)NPTS * 128];
__device__ float g_part[NBLK * 128];
__device__ float g_partsq[NBLK * 128];
__device__ float g_scale[128];
__device__ float g_shift[128];

// ---------------- small helpers: packed f32x2 FMA ---------------------------
__device__ __forceinline__ unsigned long long pack_dup(float a) {
    unsigned long long r;
    asm("mov.b64 %0, {%1, %1};" : "=l"(r) : "f"(a));
    return r;
}
__device__ __forceinline__ void fma2(unsigned long long& acc,
                                     unsigned long long a,
                                     unsigned long long b) {
    asm("fma.rn.f32x2 %0, %1, %2, %0;" : "+l"(acc) : "l"(a), "l"(b));
}
__device__ __forceinline__ float2 unpack2(unsigned long long v) {
    float lo, hi;
    asm("mov.b64 {%0, %1}, %2;" : "=f"(lo), "=f"(hi) : "l"(v));
    return make_float2(lo, hi);
}

// ---------------- map / neighbor construction ------------------------------
__global__ void init_map_kernel() {
    int i = blockIdx.x * 256 + threadIdx.x;
    g_map[i] = -1;
}

__global__ void scatter_map_kernel(const int* __restrict__ idxs) {
    int n = blockIdx.x * 256 + threadIdx.x;
    int b = idxs[4*n+0], z = idxs[4*n+1], y = idxs[4*n+2], x = idxs[4*n+3];
    g_map[((b*DD + z)*DD + y)*DD + x] = n;
}

__global__ void build_nbr_kernel(const int* __restrict__ idxs) {
    int tid = blockIdx.x * 256 + threadIdx.x;   // < 27*NPTS
    int k = tid / NPTS;
    int n = tid - k * NPTS;
    int b = idxs[4*n+0], z = idxs[4*n+1], y = idxs[4*n+2], x = idxs[4*n+3];
    int zz = z + k/9 - 1;
    int yy = y + (k/3)%3 - 1;
    int xx = x + (k%3) - 1;
    int r = -1;
    if ((unsigned)zz < (unsigned)DD && (unsigned)yy < (unsigned)DD &&
        (unsigned)xx < (unsigned)DD)
        r = g_map[((b*DD + zz)*DD + yy)*DD + xx];
    g_nbr[tid] = r;
}

// ---------------- implicit-GEMM sparse conv ---------------------------------
// out[row, co] = bias[co] + sum_k sum_ci feat[nbr[k][row], ci] * W[k, ci, co]
// BM=128 rows per block, 256 threads, per-thread 8 rows x (COUT/16) cols,
// fp32x2 packed FMAs. Writes conv output (pre-BN) + per-block sum/sumsq.
template <int CIN, int COUT>
__global__ void __launch_bounds__(256)
conv_kernel(const float* __restrict__ feat,
            const float* __restrict__ W,
            const float* __restrict__ bias) {
    constexpr int BK   = (CIN < 64) ? CIN : 64;
    constexpr int KCH  = CIN / BK;
    constexpr int TN   = COUT / 16;       // 4 or 8
    constexpr int SEGS = BK / 4;

    extern __shared__ float sm[];
    float* As = sm;                       // [BK][BM] swizzled
    float* Bs = sm + BK * BM;             // [BK][COUT]
    __shared__ int sN[BM];

    const int t  = threadIdx.x;
    const int tr = t >> 4;                // 0..15 (row group)
    const int tc = t & 15;                // 0..15 (col group)
    const int rowBase = blockIdx.x * BM;

    unsigned long long acc[8][TN/2];
#pragma unroll
    for (int i = 0; i < 8; i++)
#pragma unroll
        for (int j = 0; j < TN/2; j++) acc[i][j] = 0ull;

    for (int k = 0; k < 27; k++) {
        __syncthreads();
        if (t < BM) sN[t] = g_nbr[k * NPTS + rowBase + t];
        __syncthreads();
#pragma unroll
        for (int kc = 0; kc < KCH; kc++) {
            if (kc) __syncthreads();
            // --- gather A tile: BM rows x BK channels, transposed + swizzled
#pragma unroll
            for (int f = t; f < BM * SEGS; f += 256) {
                int row = f / SEGS;
                int seg = f - row * SEGS;
                int nb  = sN[row];
                float4 v = make_float4(0.f, 0.f, 0.f, 0.f);
                if (nb >= 0)
                    v = *reinterpret_cast<const float4*>(
                        feat + (size_t)nb * CIN + kc * BK + seg * 4);
                int rs = row ^ ((seg & 3) << 3);   // bank swizzle
                As[(seg*4+0)*BM + rs] = v.x;
                As[(seg*4+1)*BM + rs] = v.y;
                As[(seg*4+2)*BM + rs] = v.z;
                As[(seg*4+3)*BM + rs] = v.w;
            }
            // --- load W slab (contiguous [BK][COUT])
            const float4* Wk = reinterpret_cast<const float4*>(
                W + ((size_t)k * CIN + kc * BK) * COUT);
#pragma unroll
            for (int f = t; f < BK * COUT / 4; f += 256)
                reinterpret_cast<float4*>(Bs)[f] = Wk[f];
            __syncthreads();
            // --- compute
#pragma unroll 8
            for (int kk = 0; kk < BK; kk++) {
                int rbase = (tr * 8) ^ (((kk >> 2) & 3) << 3);
                float4 a0 = *reinterpret_cast<const float4*>(&As[kk*BM + rbase]);
                float4 a1 = *reinterpret_cast<const float4*>(&As[kk*BM + rbase + 4]);
                unsigned long long ad[8];
                ad[0] = pack_dup(a0.x); ad[1] = pack_dup(a0.y);
                ad[2] = pack_dup(a0.z); ad[3] = pack_dup(a0.w);
                ad[4] = pack_dup(a1.x); ad[5] = pack_dup(a1.y);
                ad[6] = pack_dup(a1.z); ad[7] = pack_dup(a1.w);
                unsigned long long bb[TN/2];
                const ulonglong2* bp = reinterpret_cast<const ulonglong2*>(
                    &Bs[kk * COUT + tc * TN]);
                {
                    ulonglong2 b0 = bp[0];
                    bb[0] = b0.x; bb[1] = b0.y;
                    if constexpr (TN == 8) {
                        ulonglong2 b1 = bp[1];
                        bb[2] = b1.x; bb[3] = b1.y;
                    }
                }
#pragma unroll
                for (int i = 0; i < 8; i++)
#pragma unroll
                    for (int j = 0; j < TN/2; j++)
                        fma2(acc[i][j], ad[i], bb[j]);
            }
        }
    }

    // ---------------- epilogue: +bias, store, per-block BN partials ---------
    float bv[TN];
#pragma unroll
    for (int j = 0; j < TN; j++) bv[j] = bias[tc * TN + j];
    float cs[TN], cq[TN];
#pragma unroll
    for (int j = 0; j < TN; j++) { cs[j] = 0.f; cq[j] = 0.f; }

#pragma unroll
    for (int i = 0; i < 8; i++) {
        float yv[TN];
#pragma unroll
        for (int j = 0; j < TN/2; j++) {
            float2 p = unpack2(acc[i][j]);
            yv[2*j]   = p.x + bv[2*j];
            yv[2*j+1] = p.y + bv[2*j+1];
        }
#pragma unroll
        for (int j = 0; j < TN; j++) { cs[j] += yv[j]; cq[j] += yv[j]*yv[j]; }
        int row = rowBase + tr * 8 + i;
#pragma unroll
        for (int j = 0; j < TN; j += 4) {
            float4 o = make_float4(yv[j], yv[j+1], yv[j+2], yv[j+3]);
            *reinterpret_cast<float4*>(
                &g_conv[(size_t)row * COUT + tc * TN + j]) = o;
        }
    }

    __syncthreads();   // done reading As; reuse as reduction scratch
#pragma unroll
    for (int j = 0; j < TN; j++) As[tr * COUT + tc * TN + j] = cs[j];
    __syncthreads();
    if (t < COUT) {
        float s = 0.f;
#pragma unroll
        for (int r = 0; r < 16; r++) s += As[r * COUT + t];
        g_part[blockIdx.x * COUT + t] = s;
    }
    __syncthreads();
#pragma unroll
    for (int j = 0; j < TN; j++) As[tr * COUT + tc * TN + j] = cq[j];
    __syncthreads();
    if (t < COUT) {
        float s = 0.f;
#pragma unroll
        for (int r = 0; r < 16; r++) s += As[r * COUT + t];
        g_partsq[blockIdx.x * COUT + t] = s;
    }
}

// ---------------- BN statistics (deterministic fixed-order reduce) ----------
__global__ void bn_reduce_kernel(const float* __restrict__ gamma,
                                 const float* __restrict__ beta, int cout) {
    __shared__ float ss[256], sq[256];
    int c = blockIdx.x;
    int t = threadIdx.x;
    float s = 0.f, q = 0.f;
    for (int b = t; b < NBLK; b += 256) {
        s += g_part[b * cout + c];
        q += g_partsq[b * cout + c];
    }
    ss[t] = s; sq[t] = q;
    __syncthreads();
    for (int o = 128; o > 0; o >>= 1) {
        if (t < o) { ss[t] += ss[t + o]; sq[t] += sq[t + o]; }
        __syncthreads();
    }
    if (t == 0) {
        float mean = ss[0] * INVN;
        float var  = sq[0] * INVN - mean * mean;
        float sc   = gamma[c] * rsqrtf(var + BN_EPS);
        g_scale[c] = sc;
        g_shift[c] = beta[c] - mean * sc;
    }
}

// ---------------- BN apply + ReLU (feeds next layer) ------------------------
template <int COUT>
__global__ void bnrelu_kernel() {
    int idx = blockIdx.x * 256 + threadIdx.x;   // < NPTS*COUT
    int c = idx & (COUT - 1);
    float v = fmaf(g_conv[idx], g_scale[c], g_shift[c]);
    g_feat[idx] = v > 0.f ? v : 0.f;
}

// ---------------- final dense scatter [B,64,12,12,12] -----------------------
__global__ void final_out_kernel(float* __restrict__ out) {
    int idx = blockIdx.x * 256 + threadIdx.x;   // output-linear -> coalesced
    int lin = idx % VOLPB;
    int bc  = idx / VOLPB;
    int c = bc & 63;
    int b = bc >> 6;
    int row = g_map[b * VOLPB + lin];
    float v = 0.f;
    if (row >= 0) {
        float y = fmaf(g_conv[(size_t)row * 64 + c], g_scale[c], g_shift[c]);
        v = y > 0.f ? y : 0.f;
    }
    out[idx] = v;
}

// ---------------- launch ----------------------------------------------------
extern "C" void kernel_launch(void* const* d_in, const int* in_sizes, int n_in,
                              void* d_out, int out_size) {
    (void)out_size;
    // inputs: features, indices, [batch_size], W0,b0,g0,be0, W1,..., W2,...
    int base = (n_in >= 15) ? 3 : 2;   // robust to scalar batch_size presence
    const float* features = (const float*)d_in[0];
    const int*   indices  = (const int*)d_in[1];
    const float* W0  = (const float*)d_in[base + 0];
    const float* b0  = (const float*)d_in[base + 1];
    const float* ga0 = (const float*)d_in[base + 2];
    const float* be0 = (const float*)d_in[base + 3];
    const float* W1  = (const float*)d_in[base + 4];
    const float* b1  = (const float*)d_in[base + 5];
    const float* ga1 = (const float*)d_in[base + 6];
    const float* be1 = (const float*)d_in[base + 7];
    const float* W2  = (const float*)d_in[base + 8];
    const float* b2  = (const float*)d_in[base + 9];
    const float* ga2 = (const float*)d_in[base + 10];
    const float* be2 = (const float*)d_in[base + 11];
    float* out = (float*)d_out;
    (void)in_sizes;

    float* featp = nullptr;
    cudaGetSymbolAddress((void**)&featp, g_feat);

    constexpr int SM0 = (16 * BM + 16 * 64) * 4;    // 12.0 KB
    constexpr int SM1 = (64 * BM + 64 * 128) * 4;   // 64.0 KB
    constexpr int SM2 = (64 * BM + 64 * 64) * 4;    // 48.0 KB
    cudaFuncSetAttribute(conv_kernel<16, 64>,
                         cudaFuncAttributeMaxDynamicSharedMemorySize, SM0);
    cudaFuncSetAttribute(conv_kernel<64, 128>,
                         cudaFuncAttributeMaxDynamicSharedMemorySize, SM1);
    cudaFuncSetAttribute(conv_kernel<128, 64>,
                         cudaFuncAttributeMaxDynamicSharedMemorySize, SM2);

    init_map_kernel<<<NVOX / 256, 256>>>();
    scatter_map_kernel<<<NPTS / 256, 256>>>(indices);
    build_nbr_kernel<<<27 * NPTS / 256, 256>>>(indices);

    // layer 0: 16 -> 64
    conv_kernel<16, 64><<<NBLK, 256, SM0>>>(features, W0, b0);
    bn_reduce_kernel<<<64, 256>>>(ga0, be0, 64);
    bnrelu_kernel<64><<<NPTS * 64 / 256, 256>>>();

    // layer 1: 64 -> 128
    conv_kernel<64, 128><<<NBLK, 256, SM1>>>(featp, W1, b1);
    bn_reduce_kernel<<<128, 256>>>(ga1, be1, 128);
    bnrelu_kernel<128><<<NPTS * 128 / 256, 256>>>();

    // layer 2: 128 -> 64
    conv_kernel<128, 64><<<NBLK, 256, SM2>>>(featp, W2, b2);
    bn_reduce_kernel<<<64, 256>>>(ga2, be2, 64);

    // final BN+ReLU+scatter, output-linear (coalesced stores)
    final_out_kernel<<<(BATCH * 64 * VOLPB) / 256, 256>>>(out);
}

// round 6
// speedup vs baseline: 1.3586x; 1.3586x over previous
#include <cuda_runtime.h>
#include <cuda_bf16.h>
#include <cstdint>

#define DD     12
#define VOLPB  1728
#define BATCH  512
#define NPTS   442368
#define NVOX   884736
#define BM     128
#define NBLK   3456
#define INVN   (1.0f/442368.0f)
#define BN_EPS 1e-5f
#define CONV_GRID 432

#if defined(__CUDA_ARCH__) && (defined(__CUDA_ARCH_FEAT_SM103_ALL) || \
    defined(__CUDA_ARCH_FEAT_SM100_ALL) || defined(__CUDA_ARCH_FEAT_SM101_ALL))
#define HAS_TCGEN05 1
#else
#define HAS_TCGEN05 0
#endif

// ---------------- device scratch (256B-aligned: vector-access safety) -------
__device__ __align__(256) int            g_map[NVOX];
__device__ __align__(256) int            g_nbr[27 * NPTS];
__device__ __align__(256) float          g_feat[(size_t)NPTS * 128];
__device__ __align__(256) __nv_bfloat16  g_fh[(size_t)NPTS * 128];
__device__ __align__(256) __nv_bfloat16  g_fl[(size_t)NPTS * 128];
__device__ __align__(256) float          g_conv[(size_t)NPTS * 128];
__device__ __align__(256) __nv_bfloat16  g_Wh[3456 * 64];
__device__ __align__(256) __nv_bfloat16  g_Wl[3456 * 64];
__device__ __align__(256) float          g_Wf[3456 * 64];
__device__ __align__(256) float          g_part[NBLK * 128];
__device__ __align__(256) float          g_partsq[NBLK * 128];
__device__ __align__(256) float          g_scale[128];
__device__ __align__(256) float          g_shift[128];

// ---------------- generic helpers ----------------
__device__ __forceinline__ uint32_t smem_u32(const void* p) {
    uint32_t a;
    asm("{ .reg .u64 t; cvta.to.shared.u64 t, %1; cvt.u32.u64 %0, t; }"
        : "=r"(a) : "l"(p));
    return a;
}

#if HAS_TCGEN05
// ---------------- tcgen05 helpers (guarded) ----------------
__device__ __forceinline__ bool elect_one() {
    uint32_t pred;
    asm volatile("{\n\t.reg .pred p;\n\telect.sync _|p, 0xFFFFFFFF;\n\t"
                 "selp.b32 %0, 1, 0, p;\n\t}" : "=r"(pred));
    return pred != 0;
}
__device__ __forceinline__ void mbar_init(uint32_t addr, uint32_t cnt) {
    asm volatile("mbarrier.init.shared.b64 [%0], %1;" :: "r"(addr), "r"(cnt)
                 : "memory");
}
__device__ __forceinline__ void mbar_wait(uint32_t addr, uint32_t phase) {
    asm volatile(
        "{\n\t.reg .pred P;\n\t"
        "W%=:\n\t"
        "mbarrier.try_wait.parity.acquire.cta.shared::cta.b64 P, [%0], %1, 0x989680;\n\t"
        "@!P bra W%=;\n\t}"
        :: "r"(addr), "r"(phase) : "memory");
}
__device__ __forceinline__ void tmem_alloc(uint32_t dst_smem, uint32_t ncols) {
    asm volatile("tcgen05.alloc.cta_group::1.sync.aligned.shared::cta.b32 [%0], %1;"
                 :: "r"(dst_smem), "r"(ncols) : "memory");
}
__device__ __forceinline__ void tmem_relinquish() {
    asm volatile("tcgen05.relinquish_alloc_permit.cta_group::1.sync.aligned;");
}
__device__ __forceinline__ void tmem_dealloc(uint32_t base, uint32_t ncols) {
    asm volatile("tcgen05.dealloc.cta_group::1.sync.aligned.b32 %0, %1;"
                 :: "r"(base), "r"(ncols));
}
__device__ __forceinline__ void fence_proxy_async_sc() {
    asm volatile("fence.proxy.async.shared::cta;" ::: "memory");
}
__device__ __forceinline__ void tc_fence_after() {
    asm volatile("tcgen05.fence::after_thread_sync;" ::: "memory");
}
__device__ __forceinline__ void tc_fence_before() {
    asm volatile("tcgen05.fence::before_thread_sync;" ::: "memory");
}
__device__ __forceinline__ void tc_wait_ld() {
    asm volatile("tcgen05.wait::ld.sync.aligned;" ::: "memory");
}
__device__ __forceinline__ void tc_commit(uint32_t mbar) {
    asm volatile(
        "tcgen05.commit.cta_group::1.mbarrier::arrive::one.shared::cluster.b64 [%0];"
        :: "r"(mbar) : "memory");
}
__device__ __forceinline__ void mma_ss_bf16(uint32_t d, uint64_t ad, uint64_t bd,
                                            uint32_t idesc, uint32_t en) {
    asm volatile(
        "{\n\t.reg .pred p;\n\tsetp.ne.u32 p, %4, 0;\n\t"
        "tcgen05.mma.cta_group::1.kind::f16 [%0], %1, %2, %3, {%5,%5,%5,%5}, p;\n\t}"
        :: "r"(d), "l"(ad), "l"(bd), "r"(idesc), "r"(en), "r"(0u) : "memory");
}
__device__ __forceinline__ void ldtm_x32(uint32_t* r, uint32_t addr) {
    asm volatile(
        "tcgen05.ld.sync.aligned.32x32b.x32.b32 "
        "{%0, %1, %2, %3, %4, %5, %6, %7, "
        " %8, %9, %10, %11, %12, %13, %14, %15, "
        " %16, %17, %18, %19, %20, %21, %22, %23, "
        " %24, %25, %26, %27, %28, %29, %30, %31}, [%32];"
        : "=r"(r[0]),  "=r"(r[1]),  "=r"(r[2]),  "=r"(r[3]),
          "=r"(r[4]),  "=r"(r[5]),  "=r"(r[6]),  "=r"(r[7]),
          "=r"(r[8]),  "=r"(r[9]),  "=r"(r[10]), "=r"(r[11]),
          "=r"(r[12]), "=r"(r[13]), "=r"(r[14]), "=r"(r[15]),
          "=r"(r[16]), "=r"(r[17]), "=r"(r[18]), "=r"(r[19]),
          "=r"(r[20]), "=r"(r[21]), "=r"(r[22]), "=r"(r[23]),
          "=r"(r[24]), "=r"(r[25]), "=r"(r[26]), "=r"(r[27]),
          "=r"(r[28]), "=r"(r[29]), "=r"(r[30]), "=r"(r[31])
        : "r"(addr));
}
__device__ __forceinline__ uint64_t mk_desc(uint32_t addr) {
    const uint64_t base = (2ull << 61) | (1ull << 46) | (64ull << 32) | (1ull << 16);
    return base | ((addr >> 4) & 0x3FFF);
}
#else
// ---------------- fallback helpers: packed f32x2 FMA ----------------
__device__ __forceinline__ unsigned long long pack_dup(float a) {
    unsigned long long r;
    asm("mov.b64 %0, {%1, %1};" : "=l"(r) : "f"(a));
    return r;
}
__device__ __forceinline__ void fma2(unsigned long long& acc,
                                     unsigned long long a,
                                     unsigned long long b) {
    asm("fma.rn.f32x2 %0, %1, %2, %0;" : "+l"(acc) : "l"(a), "l"(b));
}
__device__ __forceinline__ float2 unpack2(unsigned long long v) {
    float lo, hi;
    asm("mov.b64 {%0, %1}, %2;" : "=f"(lo), "=f"(hi) : "l"(v));
    return make_float2(lo, hi);
}
#endif

// ---------------- map / neighbor construction ----------------
__global__ void init_map_kernel() {
    g_map[blockIdx.x * 256 + threadIdx.x] = -1;
}
__global__ void scatter_map_kernel(const int* __restrict__ idxs) {
    int n = blockIdx.x * 256 + threadIdx.x;
    int b = idxs[4*n+0], z = idxs[4*n+1], y = idxs[4*n+2], x = idxs[4*n+3];
    g_map[((b*DD + z)*DD + y)*DD + x] = n;
}
__global__ void build_nbr_kernel(const int* __restrict__ idxs) {
    int tid = blockIdx.x * 256 + threadIdx.x;
    int k = tid / NPTS;
    int n = tid - k * NPTS;
    int b = idxs[4*n+0], z = idxs[4*n+1], y = idxs[4*n+2], x = idxs[4*n+3];
    int zz = z + k/9 - 1, yy = y + (k/3)%3 - 1, xx = x + (k%3) - 1;
    int r = -1;
    if ((unsigned)zz < DD && (unsigned)yy < DD && (unsigned)xx < DD)
        r = g_map[((b*DD + zz)*DD + yy)*DD + xx];
    g_nbr[tid] = r;
}

// ---------------- feature/weight bf16 split prep ----------------
__global__ void feat_split_kernel(const float* __restrict__ f) {
    int i = blockIdx.x * 256 + threadIdx.x;         // < NPTS*16
    float v = f[i];
    __nv_bfloat16 h = __float2bfloat16(v);
    g_fh[i] = h;
    g_fl[i] = __float2bfloat16(v - __bfloat162float(h));
}

// W[off][ci][co] -> bf16 split (SW128 pre-swizzled) + fp32 copy
template <int CIN, int COUT, int BK, int KCH>
__global__ void wsplit_kernel(const float* __restrict__ W) {
    int idx = blockIdx.x * 256 + threadIdx.x;       // < 27*KCH*COUT*64
    int ci   = idx & 63;
    int rowI = idx >> 6;
    int co   = rowI % COUT;
    int c    = rowI / COUT;
    int off = c / KCH, kc = c % KCH;
    int cig = kc * 64 + ci;
    float v = 0.f;
    if (ci < BK) v = W[((size_t)(off * CIN + cig)) * COUT + co];
    __nv_bfloat16 h = __float2bfloat16(v);
    __nv_bfloat16 l = __float2bfloat16(v - __bfloat162float(h));
    int dst = rowI * 64 + ((((ci >> 3) ^ (co & 7)) << 3) | (ci & 7));
    g_Wh[dst] = h;
    g_Wl[dst] = l;
    if (ci < BK)
        g_Wf[((size_t)c * BK + ci) * COUT + co] = v;
}

// ---------------- conv: tcgen05 path OR scalar fallback ----------------
template <int CIN, int COUT, int BK, int KCH>
__global__ void __launch_bounds__(256)
conv_kernel(const float* __restrict__ featF,
            const float* __restrict__ bias) {
#if HAS_TCGEN05
    constexpr int C     = 27 * KCH;
    constexpr int NK    = BK / 16;
    constexpr int CSEG  = BK / 8;
    constexpr int ATILE = 128 * 128;
    constexpr int BTILE = COUT * 128;
    constexpr uint32_t IDESC =
        (1u << 4) | (1u << 7) | (1u << 10) | ((COUT / 8) << 17) | (8u << 24);

    extern __shared__ __align__(16) char dsm_raw[];
    __shared__ __align__(8) unsigned long long s_mbar;
    __shared__ uint32_t s_tmem;
    __shared__ float sP[4][128], sQ[4][128];

    char* smp = (char*)((((uintptr_t)dsm_raw) + 1023) & ~(uintptr_t)1023);
    const uint32_t smu = smem_u32(smp);

    const int t    = threadIdx.x;
    const int wid  = t >> 5;
    const int lane = t & 31;

    if (wid == 0) {
        tmem_alloc(smem_u32(&s_tmem), COUT);
        tmem_relinquish();                 // free the permit for peer CTAs
    }
    if (t == 0) mbar_init(smem_u32(&s_mbar), 1);
    __syncthreads();
    const uint32_t tmem = s_tmem;
    const uint32_t mb   = smem_u32(&s_mbar);

    const int r    = t >> 1;                 // gather row 0..127
    const int half = t & 1;                  // 0 = hi, 1 = lo

    uint32_t ph = 0;

    for (int tile = blockIdx.x; tile < NBLK; tile += gridDim.x) {
        const int rowBase = tile * BM;

        for (int c = 0; c < C; ++c) {
            // ---- B copy (pre-swizzled, contiguous)
            {
                const float4* sh = (const float4*)(g_Wh + (size_t)c * COUT * 64);
                const float4* sl = (const float4*)(g_Wl + (size_t)c * COUT * 64);
                float4* dh = (float4*)(smp + 2 * ATILE);
                float4* dl = (float4*)(smp + 2 * ATILE + BTILE);
                #pragma unroll
                for (int i = 0; i < BTILE / 16 / 256; ++i) {
                    dh[t + i * 256] = sh[t + i * 256];
                    dl[t + i * 256] = sl[t + i * 256];
                }
            }
            // ---- A gather (SW128 rows of 128B; 2 threads per row: hi/lo)
            {
                const int off = c / KCH, kc = c % KCH;
                const int nb  = g_nbr[off * NPTS + rowBase + r];
                const __nv_bfloat16* fp = half ? g_fl : g_fh;
                const float4* src =
                    (const float4*)(fp + (size_t)(nb < 0 ? 0 : nb) * CIN + kc * 64);
                float4* dA = (float4*)(smp + half * ATILE + r * 128);
                const float4 z = make_float4(0.f, 0.f, 0.f, 0.f);
                #pragma unroll
                for (int s = 0; s < 8; ++s) {
                    float4 v = (nb >= 0 && s < CSEG) ? src[s] : z;
                    dA[s ^ (r & 7)] = v;
                }
            }
            fence_proxy_async_sc();
            __syncthreads();

            if (wid == 0) {
                tc_fence_after();
                if (elect_one()) {
                    uint64_t dAh = mk_desc(smu);
                    uint64_t dAl = mk_desc(smu + ATILE);
                    uint64_t dBh = mk_desc(smu + 2 * ATILE);
                    uint64_t dBl = mk_desc(smu + 2 * ATILE + BTILE);
                    #pragma unroll
                    for (int ks = 0; ks < NK; ++ks)
                        mma_ss_bf16(tmem, dAh + ks * 2, dBh + ks * 2, IDESC,
                                    (c == 0 && ks == 0) ? 0u : 1u);
                    #pragma unroll
                    for (int ks = 0; ks < NK; ++ks)
                        mma_ss_bf16(tmem, dAh + ks * 2, dBl + ks * 2, IDESC, 1u);
                    #pragma unroll
                    for (int ks = 0; ks < NK; ++ks)
                        mma_ss_bf16(tmem, dAl + ks * 2, dBh + ks * 2, IDESC, 1u);
                    tc_commit(mb);
                }
            }
            // synchronous: everyone waits for this chunk's MMAs to finish
            mbar_wait(mb, ph);
            ph ^= 1;
            __syncthreads();
        }

        // ---------------- epilogue: warps 0-3 only (matches examples) ------
        tc_fence_after();
        if (wid < 4) {
            const int row = rowBase + wid * 32 + lane;
            #pragma unroll
            for (int p = 0; p < COUT / 32; ++p) {
                uint32_t dr[32];
                ldtm_x32(dr, tmem + (uint32_t)(p * 32));   // plain address
                tc_wait_ld();
                #pragma unroll
                for (int j = 0; j < 32; j += 4) {
                    float y[4];
                    #pragma unroll
                    for (int q = 0; q < 4; ++q) {
                        int col = p * 32 + j + q;
                        y[q] = __uint_as_float(dr[j + q]) + __ldg(bias + col);
                        float s = y[q], qq = y[q] * y[q];
                        #pragma unroll
                        for (int o = 16; o; o >>= 1) {
                            s  += __shfl_xor_sync(0xffffffffu, s, o);
                            qq += __shfl_xor_sync(0xffffffffu, qq, o);
                        }
                        if (lane == (col & 31)) {
                            sP[wid][col] = s;
                            sQ[wid][col] = qq;
                        }
                    }
                    *(float4*)(&g_conv[(size_t)row * COUT + p * 32 + j]) =
                        make_float4(y[0], y[1], y[2], y[3]);
                }
            }
            tc_fence_before();
        }
        __syncthreads();
        if (t < COUT) {
            g_part[(size_t)tile * COUT + t] =
                sP[0][t] + sP[1][t] + sP[2][t] + sP[3][t];
            g_partsq[(size_t)tile * COUT + t] =
                sQ[0][t] + sQ[1][t] + sQ[2][t] + sQ[3][t];
        }
        __syncthreads();
    }

    __syncthreads();
    if (wid == 0) tmem_dealloc(tmem, COUT);

#else  // ------------------- scalar FFMA fallback (no tcgen05) -------------
    constexpr int TN   = COUT / 16;
    constexpr int SEGS = BK / 4;

    extern __shared__ __align__(16) float sm[];
    float* As = sm;                       // [BK][BM] swizzled
    float* Bs = sm + BK * BM;             // [BK][COUT]
    __shared__ int sN[BM];

    const int t  = threadIdx.x;
    const int tr = t >> 4;
    const int tc = t & 15;

    for (int tile = blockIdx.x; tile < NBLK; tile += gridDim.x) {
        const int rowBase = tile * BM;

        unsigned long long acc[8][TN/2];
        #pragma unroll
        for (int i = 0; i < 8; i++)
            #pragma unroll
            for (int j = 0; j < TN/2; j++) acc[i][j] = 0ull;

        for (int k = 0; k < 27; k++) {
            __syncthreads();
            if (t < BM) sN[t] = g_nbr[k * NPTS + rowBase + t];
            __syncthreads();
            #pragma unroll
            for (int kc = 0; kc < KCH; kc++) {
                if (kc) __syncthreads();
                #pragma unroll
                for (int f = t; f < BM * SEGS; f += 256) {
                    int row = f / SEGS;
                    int seg = f - row * SEGS;
                    int nb  = sN[row];
                    float4 v = make_float4(0.f, 0.f, 0.f, 0.f);
                    if (nb >= 0)
                        v = *reinterpret_cast<const float4*>(
                            featF + (size_t)nb * CIN + kc * BK + seg * 4);
                    int rs = row ^ ((seg & 3) << 3);
                    As[(seg*4+0)*BM + rs] = v.x;
                    As[(seg*4+1)*BM + rs] = v.y;
                    As[(seg*4+2)*BM + rs] = v.z;
                    As[(seg*4+3)*BM + rs] = v.w;
                }
                const float4* Wk = (const float4*)(
                    g_Wf + ((size_t)(k * KCH + kc)) * BK * COUT);
                #pragma unroll
                for (int f = t; f < BK * COUT / 4; f += 256)
                    reinterpret_cast<float4*>(Bs)[f] = Wk[f];
                __syncthreads();
                #pragma unroll 8
                for (int kk = 0; kk < BK; kk++) {
                    int rbase = (tr * 8) ^ (((kk >> 2) & 3) << 3);
                    float4 a0 = *reinterpret_cast<const float4*>(&As[kk*BM + rbase]);
                    float4 a1 = *reinterpret_cast<const float4*>(&As[kk*BM + rbase + 4]);
                    unsigned long long ad[8];
                    ad[0] = pack_dup(a0.x); ad[1] = pack_dup(a0.y);
                    ad[2] = pack_dup(a0.z); ad[3] = pack_dup(a0.w);
                    ad[4] = pack_dup(a1.x); ad[5] = pack_dup(a1.y);
                    ad[6] = pack_dup(a1.z); ad[7] = pack_dup(a1.w);
                    unsigned long long bb[TN/2];
                    const ulonglong2* bp = reinterpret_cast<const ulonglong2*>(
                        &Bs[kk * COUT + tc * TN]);
                    {
                        ulonglong2 b0 = bp[0];
                        bb[0] = b0.x; bb[1] = b0.y;
                        if constexpr (TN == 8) {
                            ulonglong2 b1 = bp[1];
                            bb[2] = b1.x; bb[3] = b1.y;
                        }
                    }
                    #pragma unroll
                    for (int i = 0; i < 8; i++)
                        #pragma unroll
                        for (int j = 0; j < TN/2; j++)
                            fma2(acc[i][j], ad[i], bb[j]);
                }
            }
        }

        float bv[TN];
        #pragma unroll
        for (int j = 0; j < TN; j++) bv[j] = bias[tc * TN + j];
        float cs[TN], cq[TN];
        #pragma unroll
        for (int j = 0; j < TN; j++) { cs[j] = 0.f; cq[j] = 0.f; }

        #pragma unroll
        for (int i = 0; i < 8; i++) {
            float yv[TN];
            #pragma unroll
            for (int j = 0; j < TN/2; j++) {
                float2 p = unpack2(acc[i][j]);
                yv[2*j]   = p.x + bv[2*j];
                yv[2*j+1] = p.y + bv[2*j+1];
            }
            #pragma unroll
            for (int j = 0; j < TN; j++) { cs[j] += yv[j]; cq[j] += yv[j]*yv[j]; }
            int row = rowBase + tr * 8 + i;
            #pragma unroll
            for (int j = 0; j < TN; j += 4) {
                float4 o = make_float4(yv[j], yv[j+1], yv[j+2], yv[j+3]);
                *reinterpret_cast<float4*>(
                    &g_conv[(size_t)row * COUT + tc * TN + j]) = o;
            }
        }

        __syncthreads();
        #pragma unroll
        for (int j = 0; j < TN; j++) As[tr * COUT + tc * TN + j] = cs[j];
        __syncthreads();
        if (t < COUT) {
            float s = 0.f;
            #pragma unroll
            for (int rr = 0; rr < 16; rr++) s += As[rr * COUT + t];
            g_part[(size_t)tile * COUT + t] = s;
        }
        __syncthreads();
        #pragma unroll
        for (int j = 0; j < TN; j++) As[tr * COUT + tc * TN + j] = cq[j];
        __syncthreads();
        if (t < COUT) {
            float s = 0.f;
            #pragma unroll
            for (int rr = 0; rr < 16; rr++) s += As[rr * COUT + t];
            g_partsq[(size_t)tile * COUT + t] = s;
        }
        __syncthreads();
    }
#endif
}

// ---------------- BN statistics ----------------
__global__ void bn_reduce_kernel(const float* __restrict__ gamma,
                                 const float* __restrict__ beta, int cout) {
    __shared__ float ss[256], sq[256];
    int c = blockIdx.x;
    int t = threadIdx.x;
    float s = 0.f, q = 0.f;
    for (int b = t; b < NBLK; b += 256) {
        s += g_part[b * cout + c];
        q += g_partsq[b * cout + c];
    }
    ss[t] = s; sq[t] = q;
    __syncthreads();
    for (int o = 128; o > 0; o >>= 1) {
        if (t < o) { ss[t] += ss[t + o]; sq[t] += sq[t + o]; }
        __syncthreads();
    }
    if (t == 0) {
        float mean = ss[0] * INVN;
        float var  = sq[0] * INVN - mean * mean;
        float sc   = gamma[c] * rsqrtf(var + BN_EPS);
        g_scale[c] = sc;
        g_shift[c] = beta[c] - mean * sc;
    }
}

// ---------------- BN apply + ReLU -> fp32 + bf16 hi/lo ----------------
template <int COUT>
__global__ void bnrelu_kernel() {
    int i = blockIdx.x * 256 + threadIdx.x;
    int c = i & (COUT - 1);
    float v = fmaf(g_conv[i], g_scale[c], g_shift[c]);
    v = v > 0.f ? v : 0.f;
    g_feat[i] = v;
    __nv_bfloat16 h = __float2bfloat16(v);
    g_fh[i] = h;
    g_fl[i] = __float2bfloat16(v - __bfloat162float(h));
}

// ---------------- final dense scatter [B,64,12,12,12] ----------------
__global__ void final_out_kernel(float* __restrict__ out) {
    int idx = blockIdx.x * 256 + threadIdx.x;
    int lin = idx % VOLPB;
    int bc  = idx / VOLPB;
    int c = bc & 63;
    int b = bc >> 6;
    int row = g_map[b * VOLPB + lin];
    float v = 0.f;
    if (row >= 0) {
        float y = fmaf(g_conv[(size_t)row * 64 + c], g_scale[c], g_shift[c]);
        v = y > 0.f ? y : 0.f;
    }
    out[idx] = v;
}

// ---------------- launch ----------------
extern "C" void kernel_launch(void* const* d_in, const int* in_sizes, int n_in,
                              void* d_out, int out_size) {
    (void)in_sizes; (void)out_size;
    int base = (n_in >= 15) ? 3 : 2;
    const float* features = (const float*)d_in[0];
    const int*   indices  = (const int*)d_in[1];
    const float* W0  = (const float*)d_in[base + 0];
    const float* b0  = (const float*)d_in[base + 1];
    const float* ga0 = (const float*)d_in[base + 2];
    const float* be0 = (const float*)d_in[base + 3];
    const float* W1  = (const float*)d_in[base + 4];
    const float* b1  = (const float*)d_in[base + 5];
    const float* ga1 = (const float*)d_in[base + 6];
    const float* be1 = (const float*)d_in[base + 7];
    const float* W2  = (const float*)d_in[base + 8];
    const float* b2  = (const float*)d_in[base + 9];
    const float* ga2 = (const float*)d_in[base + 10];
    const float* be2 = (const float*)d_in[base + 11];
    float* out = (float*)d_out;

    float* featp = nullptr;
    cudaGetSymbolAddress((void**)&featp, g_feat);

    // single-stage tile: 2*ATILE + 2*BTILE + 1KB align slack
    constexpr int SM64  = 2 * 16384 + 2 * 64  * 128 + 1024;  // 50176
    constexpr int SM128 = 2 * 16384 + 2 * 128 * 128 + 1024;  // 66560
    cudaFuncSetAttribute(conv_kernel<16, 64, 16, 1>,
                         cudaFuncAttributeMaxDynamicSharedMemorySize, SM64);
    cudaFuncSetAttribute(conv_kernel<64, 128, 64, 1>,
                         cudaFuncAttributeMaxDynamicSharedMemorySize, SM128);
    cudaFuncSetAttribute(conv_kernel<128, 64, 64, 2>,
                         cudaFuncAttributeMaxDynamicSharedMemorySize, SM64);

    init_map_kernel<<<NVOX / 256, 256>>>();
    scatter_map_kernel<<<NPTS / 256, 256>>>(indices);
    build_nbr_kernel<<<27 * NPTS / 256, 256>>>(indices);
    feat_split_kernel<<<NPTS * 16 / 256, 256>>>(features);

    // layer 0: 16 -> 64
    wsplit_kernel<16, 64, 16, 1><<<27 * 64 * 64 / 256, 256>>>(W0);
    conv_kernel<16, 64, 16, 1><<<CONV_GRID, 256, SM64>>>(features, b0);
    bn_reduce_kernel<<<64, 256>>>(ga0, be0, 64);
    bnrelu_kernel<64><<<NPTS * 64 / 256, 256>>>();

    // layer 1: 64 -> 128
    wsplit_kernel<64, 128, 64, 1><<<27 * 128 * 64 / 256, 256>>>(W1);
    conv_kernel<64, 128, 64, 1><<<CONV_GRID, 256, SM128>>>(featp, b1);
    bn_reduce_kernel<<<128, 256>>>(ga1, be1, 128);
    bnrelu_kernel<128><<<NPTS * 128 / 256, 256>>>();

    // layer 2: 128 -> 64
    wsplit_kernel<128, 64, 64, 2><<<54 * 64 * 64 / 256, 256>>>(W2);
    conv_kernel<128, 64, 64, 2><<<CONV_GRID, 256, SM64>>>(featp, b2);
    bn_reduce_kernel<<<64, 256>>>(ga2, be2, 64);

    final_out_kernel<<<(BATCH * 64 * VOLPB) / 256, 256>>>(out);
}

// round 7
// speedup vs baseline: 1.4520x; 1.0688x over previous
#include <cuda_runtime.h>
#include <cuda_bf16.h>
#include <cstdint>

#define DD     12
#define VOLPB  1728
#define BATCH  512
#define NPTS   442368
#define NVOX   884736
#define BM     128
#define NBLK   3456
#define INVN   (1.0f/442368.0f)
#define BN_EPS 1e-5f

#if defined(__CUDA_ARCH__) && (defined(__CUDA_ARCH_FEAT_SM103_ALL) || \
    defined(__CUDA_ARCH_FEAT_SM100_ALL) || defined(__CUDA_ARCH_FEAT_SM101_ALL))
#define HAS_TCGEN05 1
#else
#define HAS_TCGEN05 0
#endif

// ---------------- device scratch ----------------
__device__ __align__(256) int            g_map[NVOX];
__device__ __align__(256) int            g_nbr[27 * NPTS];
__device__ __align__(256) float          g_feat[(size_t)NPTS * 128];
__device__ __align__(256) __nv_bfloat16  g_fh[(size_t)NPTS * 128];
__device__ __align__(256) __nv_bfloat16  g_fl[(size_t)NPTS * 128];
__device__ __align__(256) float          g_conv[(size_t)NPTS * 128];
__device__ __align__(256) __nv_bfloat16  g_Wh[3456 * 64];
__device__ __align__(256) __nv_bfloat16  g_Wl[3456 * 64];
__device__ __align__(256) float          g_Wf[3456 * 64];
__device__ __align__(256) float          g_part[NBLK * 128];
__device__ __align__(256) float          g_partsq[NBLK * 128];
__device__ __align__(256) float          g_scale[128];
__device__ __align__(256) float          g_shift[128];

// ---------------- generic helpers ----------------
__device__ __forceinline__ uint32_t smem_u32(const void* p) {
    uint32_t a;
    asm("{ .reg .u64 t; cvta.to.shared.u64 t, %1; cvt.u32.u64 %0, t; }"
        : "=r"(a) : "l"(p));
    return a;
}

#if HAS_TCGEN05
__device__ __forceinline__ bool elect_one() {
    uint32_t pred;
    asm volatile("{\n\t.reg .pred p;\n\telect.sync _|p, 0xFFFFFFFF;\n\t"
                 "selp.b32 %0, 1, 0, p;\n\t}" : "=r"(pred));
    return pred != 0;
}
__device__ __forceinline__ void mbar_init(uint32_t addr, uint32_t cnt) {
    asm volatile("mbarrier.init.shared.b64 [%0], %1;" :: "r"(addr), "r"(cnt)
                 : "memory");
}
__device__ __forceinline__ void mbar_wait(uint32_t addr, uint32_t phase) {
    asm volatile(
        "{\n\t.reg .pred P;\n\t"
        "W%=:\n\t"
        "mbarrier.try_wait.parity.acquire.cta.shared::cta.b64 P, [%0], %1, 0x989680;\n\t"
        "@!P bra W%=;\n\t}"
        :: "r"(addr), "r"(phase) : "memory");
}
__device__ __forceinline__ void tmem_alloc(uint32_t dst_smem, uint32_t ncols) {
    asm volatile("tcgen05.alloc.cta_group::1.sync.aligned.shared::cta.b32 [%0], %1;"
                 :: "r"(dst_smem), "r"(ncols) : "memory");
}
__device__ __forceinline__ void tmem_relinquish() {
    asm volatile("tcgen05.relinquish_alloc_permit.cta_group::1.sync.aligned;");
}
__device__ __forceinline__ void tmem_dealloc(uint32_t base, uint32_t ncols) {
    asm volatile("tcgen05.dealloc.cta_group::1.sync.aligned.b32 %0, %1;"
                 :: "r"(base), "r"(ncols));
}
__device__ __forceinline__ void fence_proxy_async_sc() {
    asm volatile("fence.proxy.async.shared::cta;" ::: "memory");
}
__device__ __forceinline__ void tc_fence_after() {
    asm volatile("tcgen05.fence::after_thread_sync;" ::: "memory");
}
__device__ __forceinline__ void tc_fence_before() {
    asm volatile("tcgen05.fence::before_thread_sync;" ::: "memory");
}
__device__ __forceinline__ void tc_wait_ld() {
    asm volatile("tcgen05.wait::ld.sync.aligned;" ::: "memory");
}
__device__ __forceinline__ void tc_commit(uint32_t mbar) {
    asm volatile(
        "tcgen05.commit.cta_group::1.mbarrier::arrive::one.shared::cluster.b64 [%0];"
        :: "r"(mbar) : "memory");
}
__device__ __forceinline__ void mma_ss_bf16(uint32_t d, uint64_t ad, uint64_t bd,
                                            uint32_t idesc, uint32_t en) {
    asm volatile(
        "{\n\t.reg .pred p;\n\tsetp.ne.u32 p, %4, 0;\n\t"
        "tcgen05.mma.cta_group::1.kind::f16 [%0], %1, %2, %3, {%5,%5,%5,%5}, p;\n\t}"
        :: "r"(d), "l"(ad), "l"(bd), "r"(idesc), "r"(en), "r"(0u) : "memory");
}
__device__ __forceinline__ void ldtm_x32(uint32_t* r, uint32_t addr) {
    asm volatile(
        "tcgen05.ld.sync.aligned.32x32b.x32.b32 "
        "{%0, %1, %2, %3, %4, %5, %6, %7, "
        " %8, %9, %10, %11, %12, %13, %14, %15, "
        " %16, %17, %18, %19, %20, %21, %22, %23, "
        " %24, %25, %26, %27, %28, %29, %30, %31}, [%32];"
        : "=r"(r[0]),  "=r"(r[1]),  "=r"(r[2]),  "=r"(r[3]),
          "=r"(r[4]),  "=r"(r[5]),  "=r"(r[6]),  "=r"(r[7]),
          "=r"(r[8]),  "=r"(r[9]),  "=r"(r[10]), "=r"(r[11]),
          "=r"(r[12]), "=r"(r[13]), "=r"(r[14]), "=r"(r[15]),
          "=r"(r[16]), "=r"(r[17]), "=r"(r[18]), "=r"(r[19]),
          "=r"(r[20]), "=r"(r[21]), "=r"(r[22]), "=r"(r[23]),
          "=r"(r[24]), "=r"(r[25]), "=r"(r[26]), "=r"(r[27]),
          "=r"(r[28]), "=r"(r[29]), "=r"(r[30]), "=r"(r[31])
        : "r"(addr));
}
__device__ __forceinline__ uint64_t mk_desc(uint32_t addr) {
    const uint64_t base = (2ull << 61) | (1ull << 46) | (64ull << 32) | (1ull << 16);
    return base | ((addr >> 4) & 0x3FFF);
}
#else
__device__ __forceinline__ unsigned long long pack_dup(float a) {
    unsigned long long r;
    asm("mov.b64 %0, {%1, %1};" : "=l"(r) : "f"(a));
    return r;
}
__device__ __forceinline__ void fma2(unsigned long long& acc,
                                     unsigned long long a,
                                     unsigned long long b) {
    asm("fma.rn.f32x2 %0, %1, %2, %0;" : "+l"(acc) : "l"(a), "l"(b));
}
__device__ __forceinline__ float2 unpack2(unsigned long long v) {
    float lo, hi;
    asm("mov.b64 {%0, %1}, %2;" : "=f"(lo), "=f"(hi) : "l"(v));
    return make_float2(lo, hi);
}
#endif

// ---------------- map / neighbor construction ----------------
__global__ void init_map_kernel() {
    g_map[blockIdx.x * 256 + threadIdx.x] = -1;
}
__global__ void scatter_map_kernel(const int* __restrict__ idxs) {
    int n = blockIdx.x * 256 + threadIdx.x;
    int b = idxs[4*n+0], z = idxs[4*n+1], y = idxs[4*n+2], x = idxs[4*n+3];
    g_map[((b*DD + z)*DD + y)*DD + x] = n;
}
__global__ void build_nbr_kernel(const int* __restrict__ idxs) {
    int tid = blockIdx.x * 256 + threadIdx.x;
    int k = tid / NPTS;
    int n = tid - k * NPTS;
    int b = idxs[4*n+0], z = idxs[4*n+1], y = idxs[4*n+2], x = idxs[4*n+3];
    int zz = z + k/9 - 1, yy = y + (k/3)%3 - 1, xx = x + (k%3) - 1;
    int r = -1;
    if ((unsigned)zz < DD && (unsigned)yy < DD && (unsigned)xx < DD)
        r = g_map[((b*DD + zz)*DD + yy)*DD + xx];
    g_nbr[tid] = r;
}

// ---------------- feature/weight bf16 split prep ----------------
__global__ void feat_split_kernel(const float* __restrict__ f) {
    int i = blockIdx.x * 256 + threadIdx.x;
    float v = f[i];
    __nv_bfloat16 h = __float2bfloat16(v);
    g_fh[i] = h;
    g_fl[i] = __float2bfloat16(v - __bfloat162float(h));
}

template <int CIN, int COUT, int BK, int KCH>
__global__ void wsplit_kernel(const float* __restrict__ W) {
    int idx = blockIdx.x * 256 + threadIdx.x;
    int ci   = idx & 63;
    int rowI = idx >> 6;
    int co   = rowI % COUT;
    int c    = rowI / COUT;
    int off = c / KCH, kc = c % KCH;
    int cig = kc * 64 + ci;
    float v = 0.f;
    if (ci < BK) v = W[((size_t)(off * CIN + cig)) * COUT + co];
    __nv_bfloat16 h = __float2bfloat16(v);
    __nv_bfloat16 l = __float2bfloat16(v - __bfloat162float(h));
    int dst = rowI * 64 + ((((ci >> 3) ^ (co & 7)) << 3) | (ci & 7));
    g_Wh[dst] = h;
    g_Wl[dst] = l;
    if (ci < BK)
        g_Wf[((size_t)c * BK + ci) * COUT + co] = v;
}

// ---------------- conv: tcgen05 path OR scalar fallback ----------------
// grid = NBLK / TG groups; each CTA owns TG tiles, accumulators in TMEM.
template <int CIN, int COUT, int BK, int KCH, int TG>
__global__ void __launch_bounds__(256)
conv_kernel(const float* __restrict__ featF,
            const float* __restrict__ bias) {
#if HAS_TCGEN05
    constexpr int C     = 27 * KCH;
    constexpr int NK    = BK / 16;
    constexpr int CSEG  = BK / 8;
    constexpr int ATILE = 128 * 128;          // one half (hi or lo), bytes
    constexpr int ASTG  = 2 * ATILE;          // hi+lo per stage
    constexpr int BTILE = COUT * 128;
    constexpr int CPW   = COUT / 2;
    constexpr uint32_t IDESC =
        (1u << 4) | (1u << 7) | (1u << 10) | ((COUT / 8) << 17) | (8u << 24);

    extern __shared__ __align__(16) char dsm_raw[];
    __shared__ __align__(8) unsigned long long s_mbar[2];
    __shared__ uint32_t s_tmem;
    __shared__ float sP[4][128], sQ[4][128];

    char* smp = (char*)((((uintptr_t)dsm_raw) + 1023) & ~(uintptr_t)1023);
    const uint32_t smu = smem_u32(smp);
    // layout: A stage0 (hi,lo) | A stage1 (hi,lo) | B hi | B lo
    const uint32_t aBase = smu;
    const uint32_t bBase = smu + 2 * ASTG;

    const int t    = threadIdx.x;
    const int wid  = t >> 5;
    const int lane = t & 31;

    if (wid == 0) {
        tmem_alloc(smem_u32(&s_tmem), 512);
        tmem_relinquish();
    }
    if (t == 0) { mbar_init(smem_u32(&s_mbar[0]), 1);
                  mbar_init(smem_u32(&s_mbar[1]), 1); }
    __syncthreads();
    const uint32_t tmem = s_tmem;
    const uint32_t mba[2] = { smem_u32(&s_mbar[0]), smem_u32(&s_mbar[1]) };

    const int group    = blockIdx.x;
    const int tileBase = group * TG;
    const int r    = t >> 1;
    const int half = t & 1;

    uint32_t ph[2]   = {0u, 0u};
    bool     pend[2] = {false, false};

    for (int c = 0; c < C; ++c) {
        // chunk boundary: drain both A buffers => all MMAs of prev chunk done
        // => safe to overwrite B.
        #pragma unroll
        for (int b = 0; b < 2; ++b)
            if (pend[b]) { mbar_wait(mba[b], ph[b]); ph[b] ^= 1; pend[b] = false; }

        // ---- B copy for this chunk (hi/lo, pre-swizzled contiguous)
        {
            const float4* sh = (const float4*)(g_Wh + (size_t)c * COUT * 64);
            const float4* sl = (const float4*)(g_Wl + (size_t)c * COUT * 64);
            float4* dh = (float4*)(smp + 2 * ASTG);
            float4* dl = (float4*)(smp + 2 * ASTG + BTILE);
            #pragma unroll
            for (int i = 0; i < BTILE / 16 / 256; ++i) {
                dh[t + i * 256] = sh[t + i * 256];
                dl[t + i * 256] = sl[t + i * 256];
            }
        }

        const int off = c / KCH, kc = c % KCH;

        #pragma unroll 1
        for (int j = 0; j < TG; ++j) {
            const int buf = j & 1;
            if (pend[buf]) { mbar_wait(mba[buf], ph[buf]); ph[buf] ^= 1;
                             pend[buf] = false; }

            // ---- A gather into stage buf
            {
                const int rowBase = (tileBase + j) * BM;
                const int nb  = g_nbr[off * NPTS + rowBase + r];
                const __nv_bfloat16* fp = half ? g_fl : g_fh;
                const float4* src =
                    (const float4*)(fp + (size_t)(nb < 0 ? 0 : nb) * CIN + kc * 64);
                float4* dA = (float4*)(smp + buf * ASTG + half * ATILE + r * 128);
                const float4 z = make_float4(0.f, 0.f, 0.f, 0.f);
                #pragma unroll
                for (int s = 0; s < 8; ++s) {
                    float4 v = (nb >= 0 && s < CSEG) ? src[s] : z;
                    dA[s ^ (r & 7)] = v;
                }
            }
            fence_proxy_async_sc();
            __syncthreads();

            if (wid == 0) {
                tc_fence_after();
                if (elect_one()) {
                    const uint32_t ab = aBase + buf * ASTG;
                    uint64_t dAh = mk_desc(ab);
                    uint64_t dAl = mk_desc(ab + ATILE);
                    uint64_t dBh = mk_desc(bBase);
                    uint64_t dBl = mk_desc(bBase + BTILE);
                    const uint32_t dTm = tmem + (uint32_t)(j * COUT);
                    #pragma unroll
                    for (int ks = 0; ks < NK; ++ks)
                        mma_ss_bf16(dTm, dAh + ks * 2, dBh + ks * 2, IDESC,
                                    (c == 0 && ks == 0) ? 0u : 1u);
                    #pragma unroll
                    for (int ks = 0; ks < NK; ++ks)
                        mma_ss_bf16(dTm, dAh + ks * 2, dBl + ks * 2, IDESC, 1u);
                    #pragma unroll
                    for (int ks = 0; ks < NK; ++ks)
                        mma_ss_bf16(dTm, dAl + ks * 2, dBh + ks * 2, IDESC, 1u);
                    tc_commit(mba[buf]);
                }
            }
            pend[buf] = true;
        }
    }

    // final drain
    #pragma unroll
    for (int b = 0; b < 2; ++b)
        if (pend[b]) { mbar_wait(mba[b], ph[b]); ph[b] ^= 1; pend[b] = false; }
    tc_fence_after();

    // ---------------- epilogue: all 8 warps; columns split by warpgroup -----
    const int grp     = wid >> 2;            // 0 or 1
    const int rw      = wid & 3;             // row warp 0..3
    const int colBase = grp * CPW;

    for (int j = 0; j < TG; ++j) {
        const int tile = tileBase + j;
        const int row  = tile * BM + rw * 32 + lane;
        #pragma unroll
        for (int p = 0; p < CPW / 32; ++p) {
            uint32_t dr[32];
            ldtm_x32(dr, tmem + (uint32_t)(j * COUT + colBase + p * 32));
            tc_wait_ld();
            #pragma unroll
            for (int jj = 0; jj < 32; jj += 4) {
                float y[4];
                #pragma unroll
                for (int q = 0; q < 4; ++q) {
                    int col = colBase + p * 32 + jj + q;
                    y[q] = __uint_as_float(dr[jj + q]) + __ldg(bias + col);
                    float s = y[q], qq = y[q] * y[q];
                    #pragma unroll
                    for (int o = 16; o; o >>= 1) {
                        s  += __shfl_xor_sync(0xffffffffu, s, o);
                        qq += __shfl_xor_sync(0xffffffffu, qq, o);
                    }
                    if (lane == (col & 31)) {
                        sP[rw][col] = s;
                        sQ[rw][col] = qq;
                    }
                }
                *(float4*)(&g_conv[(size_t)row * COUT + colBase + p * 32 + jj]) =
                    make_float4(y[0], y[1], y[2], y[3]);
            }
        }
        __syncthreads();
        if (t < COUT) {
            g_part[(size_t)tile * COUT + t] =
                sP[0][t] + sP[1][t] + sP[2][t] + sP[3][t];
            g_partsq[(size_t)tile * COUT + t] =
                sQ[0][t] + sQ[1][t] + sQ[2][t] + sQ[3][t];
        }
        __syncthreads();
    }
    tc_fence_before();
    __syncthreads();
    if (wid == 0) tmem_dealloc(tmem, 512);

#else  // ------------------- scalar FFMA fallback (no tcgen05) -------------
    constexpr int TN   = COUT / 16;
    constexpr int SEGS = BK / 4;

    extern __shared__ __align__(16) float sm[];
    float* As = sm;
    float* Bs = sm + BK * BM;
    __shared__ int sN[BM];

    const int t  = threadIdx.x;
    const int tr = t >> 4;
    const int tc = t & 15;

    for (int tile = blockIdx.x * TG; tile < (blockIdx.x + 1) * TG; ++tile) {
        const int rowBase = tile * BM;

        unsigned long long acc[8][TN/2];
        #pragma unroll
        for (int i = 0; i < 8; i++)
            #pragma unroll
            for (int j = 0; j < TN/2; j++) acc[i][j] = 0ull;

        for (int k = 0; k < 27; k++) {
            __syncthreads();
            if (t < BM) sN[t] = g_nbr[k * NPTS + rowBase + t];
            __syncthreads();
            #pragma unroll
            for (int kc = 0; kc < KCH; kc++) {
                if (kc) __syncthreads();
                #pragma unroll
                for (int f = t; f < BM * SEGS; f += 256) {
                    int row = f / SEGS;
                    int seg = f - row * SEGS;
                    int nb  = sN[row];
                    float4 v = make_float4(0.f, 0.f, 0.f, 0.f);
                    if (nb >= 0)
                        v = *reinterpret_cast<const float4*>(
                            featF + (size_t)nb * CIN + kc * BK + seg * 4);
                    int rs = row ^ ((seg & 3) << 3);
                    As[(seg*4+0)*BM + rs] = v.x;
                    As[(seg*4+1)*BM + rs] = v.y;
                    As[(seg*4+2)*BM + rs] = v.z;
                    As[(seg*4+3)*BM + rs] = v.w;
                }
                const float4* Wk = (const float4*)(
                    g_Wf + ((size_t)(k * KCH + kc)) * BK * COUT);
                #pragma unroll
                for (int f = t; f < BK * COUT / 4; f += 256)
                    reinterpret_cast<float4*>(Bs)[f] = Wk[f];
                __syncthreads();
                #pragma unroll 8
                for (int kk = 0; kk < BK; kk++) {
                    int rbase = (tr * 8) ^ (((kk >> 2) & 3) << 3);
                    float4 a0 = *reinterpret_cast<const float4*>(&As[kk*BM + rbase]);
                    float4 a1 = *reinterpret_cast<const float4*>(&As[kk*BM + rbase + 4]);
                    unsigned long long ad[8];
                    ad[0] = pack_dup(a0.x); ad[1] = pack_dup(a0.y);
                    ad[2] = pack_dup(a0.z); ad[3] = pack_dup(a0.w);
                    ad[4] = pack_dup(a1.x); ad[5] = pack_dup(a1.y);
                    ad[6] = pack_dup(a1.z); ad[7] = pack_dup(a1.w);
                    unsigned long long bb[TN/2];
                    const ulonglong2* bp = reinterpret_cast<const ulonglong2*>(
                        &Bs[kk * COUT + tc * TN]);
                    {
                        ulonglong2 b0 = bp[0];
                        bb[0] = b0.x; bb[1] = b0.y;
                        if constexpr (TN == 8) {
                            ulonglong2 b1 = bp[1];
                            bb[2] = b1.x; bb[3] = b1.y;
                        }
                    }
                    #pragma unroll
                    for (int i = 0; i < 8; i++)
                        #pragma unroll
                        for (int j = 0; j < TN/2; j++)
                            fma2(acc[i][j], ad[i], bb[j]);
                }
            }
        }

        float bv[TN];
        #pragma unroll
        for (int j = 0; j < TN; j++) bv[j] = bias[tc * TN + j];
        float cs[TN], cq[TN];
        #pragma unroll
        for (int j = 0; j < TN; j++) { cs[j] = 0.f; cq[j] = 0.f; }

        #pragma unroll
        for (int i = 0; i < 8; i++) {
            float yv[TN];
            #pragma unroll
            for (int j = 0; j < TN/2; j++) {
                float2 p = unpack2(acc[i][j]);
                yv[2*j]   = p.x + bv[2*j];
                yv[2*j+1] = p.y + bv[2*j+1];
            }
            #pragma unroll
            for (int j = 0; j < TN; j++) { cs[j] += yv[j]; cq[j] += yv[j]*yv[j]; }
            int row = rowBase + tr * 8 + i;
            #pragma unroll
            for (int j = 0; j < TN; j += 4) {
                float4 o = make_float4(yv[j], yv[j+1], yv[j+2], yv[j+3]);
                *reinterpret_cast<float4*>(
                    &g_conv[(size_t)row * COUT + tc * TN + j]) = o;
            }
        }

        __syncthreads();
        #pragma unroll
        for (int j = 0; j < TN; j++) As[tr * COUT + tc * TN + j] = cs[j];
        __syncthreads();
        if (t < COUT) {
            float s = 0.f;
            #pragma unroll
            for (int rr = 0; rr < 16; rr++) s += As[rr * COUT + t];
            g_part[(size_t)tile * COUT + t] = s;
        }
        __syncthreads();
        #pragma unroll
        for (int j = 0; j < TN; j++) As[tr * COUT + tc * TN + j] = cq[j];
        __syncthreads();
        if (t < COUT) {
            float s = 0.f;
            #pragma unroll
            for (int rr = 0; rr < 16; rr++) s += As[rr * COUT + t];
            g_partsq[(size_t)tile * COUT + t] = s;
        }
        __syncthreads();
    }
#endif
}

// ---------------- BN statistics ----------------
__global__ void bn_reduce_kernel(const float* __restrict__ gamma,
                                 const float* __restrict__ beta, int cout) {
    __shared__ float ss[256], sq[256];
    int c = blockIdx.x;
    int t = threadIdx.x;
    float s = 0.f, q = 0.f;
    for (int b = t; b < NBLK; b += 256) {
        s += g_part[b * cout + c];
        q += g_partsq[b * cout + c];
    }
    ss[t] = s; sq[t] = q;
    __syncthreads();
    for (int o = 128; o > 0; o >>= 1) {
        if (t < o) { ss[t] += ss[t + o]; sq[t] += sq[t + o]; }
        __syncthreads();
    }
    if (t == 0) {
        float mean = ss[0] * INVN;
        float var  = sq[0] * INVN - mean * mean;
        float sc   = gamma[c] * rsqrtf(var + BN_EPS);
        g_scale[c] = sc;
        g_shift[c] = beta[c] - mean * sc;
    }
}

// ---------------- BN apply + ReLU -> fp32 + bf16 hi/lo ----------------
template <int COUT>
__global__ void bnrelu_kernel() {
    int i = blockIdx.x * 256 + threadIdx.x;
    int c = i & (COUT - 1);
    float v = fmaf(g_conv[i], g_scale[c], g_shift[c]);
    v = v > 0.f ? v : 0.f;
    g_feat[i] = v;
    __nv_bfloat16 h = __float2bfloat16(v);
    g_fh[i] = h;
    g_fl[i] = __float2bfloat16(v - __bfloat162float(h));
}

// ---------------- final dense scatter [B,64,12,12,12] ----------------
__global__ void final_out_kernel(float* __restrict__ out) {
    int idx = blockIdx.x * 256 + threadIdx.x;
    int lin = idx % VOLPB;
    int bc  = idx / VOLPB;
    int c = bc & 63;
    int b = bc >> 6;
    int row = g_map[b * VOLPB + lin];
    float v = 0.f;
    if (row >= 0) {
        float y = fmaf(g_conv[(size_t)row * 64 + c], g_scale[c], g_shift[c]);
        v = y > 0.f ? y : 0.f;
    }
    out[idx] = v;
}

// ---------------- launch ----------------
extern "C" void kernel_launch(void* const* d_in, const int* in_sizes, int n_in,
                              void* d_out, int out_size) {
    (void)in_sizes; (void)out_size;
    int base = (n_in >= 15) ? 3 : 2;
    const float* features = (const float*)d_in[0];
    const int*   indices  = (const int*)d_in[1];
    const float* W0  = (const float*)d_in[base + 0];
    const float* b0  = (const float*)d_in[base + 1];
    const float* ga0 = (const float*)d_in[base + 2];
    const float* be0 = (const float*)d_in[base + 3];
    const float* W1  = (const float*)d_in[base + 4];
    const float* b1  = (const float*)d_in[base + 5];
    const float* ga1 = (const float*)d_in[base + 6];
    const float* be1 = (const float*)d_in[base + 7];
    const float* W2  = (const float*)d_in[base + 8];
    const float* b2  = (const float*)d_in[base + 9];
    const float* ga2 = (const float*)d_in[base + 10];
    const float* be2 = (const float*)d_in[base + 11];
    float* out = (float*)d_out;

    float* featp = nullptr;
    cudaGetSymbolAddress((void**)&featp, g_feat);

    // A: 2 stages x (hi+lo) = 64KB; B: 2 x COUT*128
    constexpr int SM64  = 4 * 16384 + 2 * 64  * 128 + 1024;  // 82944
    constexpr int SM128 = 4 * 16384 + 2 * 128 * 128 + 1024;  // 99328
    cudaFuncSetAttribute(conv_kernel<16, 64, 16, 1, 8>,
                         cudaFuncAttributeMaxDynamicSharedMemorySize, SM64);
    cudaFuncSetAttribute(conv_kernel<64, 128, 64, 1, 4>,
                         cudaFuncAttributeMaxDynamicSharedMemorySize, SM128);
    cudaFuncSetAttribute(conv_kernel<128, 64, 64, 2, 8>,
                         cudaFuncAttributeMaxDynamicSharedMemorySize, SM64);

    init_map_kernel<<<NVOX / 256, 256>>>();
    scatter_map_kernel<<<NPTS / 256, 256>>>(indices);
    build_nbr_kernel<<<27 * NPTS / 256, 256>>>(indices);
    feat_split_kernel<<<NPTS * 16 / 256, 256>>>(features);

    // layer 0: 16 -> 64 (TG=8 -> 432 groups)
    wsplit_kernel<16, 64, 16, 1><<<27 * 64 * 64 / 256, 256>>>(W0);
    conv_kernel<16, 64, 16, 1, 8><<<NBLK / 8, 256, SM64>>>(features, b0);
    bn_reduce_kernel<<<64, 256>>>(ga0, be0, 64);
    bnrelu_kernel<64><<<NPTS * 64 / 256, 256>>>();

    // layer 1: 64 -> 128 (TG=4 -> 864 groups)
    wsplit_kernel<64, 128, 64, 1><<<27 * 128 * 64 / 256, 256>>>(W1);
    conv_kernel<64, 128, 64, 1, 4><<<NBLK / 4, 256, SM128>>>(featp, b1);
    bn_reduce_kernel<<<128, 256>>>(ga1, be1, 128);
    bnrelu_kernel<128><<<NPTS * 128 / 256, 256>>>();

    // layer 2: 128 -> 64 (TG=8 -> 432 groups)
    wsplit_kernel<128, 64, 64, 2><<<54 * 64 * 64 / 256, 256>>>(W2);
    conv_kernel<128, 64, 64, 2, 8><<<NBLK / 8, 256, SM64>>>(featp, b2);
    bn_reduce_kernel<<<64, 256>>>(ga2, be2, 64);

    final_out_kernel<<<(BATCH * 64 * VOLPB) / 256, 256>>>(out);
}

// round 8
// speedup vs baseline: 2.2364x; 1.5402x over previous
#include <cuda_runtime.h>
#include <cuda_bf16.h>
#include <cstdint>

#define DD     12
#define VOLPB  1728
#define BATCH  512
#define NPTS   442368
#define NVOX   884736
#define BM     128
#define NBLK   3456
#define INVN   (1.0f/442368.0f)
#define BN_EPS 1e-5f

// weight region bases (elements)
#define WH0 0
#define WH1 110592
#define WH2 331776
#define WHTOT 552960
#define WF0 0
#define WF1 27648
#define WF2 248832
#define WFTOT 470016

#if defined(__CUDA_ARCH__) && (defined(__CUDA_ARCH_FEAT_SM103_ALL) || \
    defined(__CUDA_ARCH_FEAT_SM100_ALL) || defined(__CUDA_ARCH_FEAT_SM101_ALL))
#define HAS_TCGEN05 1
#else
#define HAS_TCGEN05 0
#endif

// ---------------- device scratch ----------------
__device__ __align__(256) int            g_map[NVOX];
__device__ __align__(256) int            g_nbr[27 * NPTS];
__device__ __align__(256) float          g_feat[(size_t)NPTS * 128];
__device__ __align__(256) __nv_bfloat16  g_fh[(size_t)NPTS * 128];
__device__ __align__(256) __nv_bfloat16  g_fl[(size_t)NPTS * 128];
__device__ __align__(256) float          g_conv[(size_t)NPTS * 128];
__device__ __align__(256) __nv_bfloat16  g_Wh[WHTOT];
__device__ __align__(256) __nv_bfloat16  g_Wl[WHTOT];
__device__ __align__(256) float          g_Wf[WFTOT];
__device__ __align__(256) float          g_part[NBLK * 128];
__device__ __align__(256) float          g_partsq[NBLK * 128];
__device__ __align__(256) float          g_scale[128];
__device__ __align__(256) float          g_shift[128];

// ---------------- generic helpers ----------------
__device__ __forceinline__ uint32_t smem_u32(const void* p) {
    uint32_t a;
    asm("{ .reg .u64 t; cvta.to.shared.u64 t, %1; cvt.u32.u64 %0, t; }"
        : "=r"(a) : "l"(p));
    return a;
}

#if HAS_TCGEN05
__device__ __forceinline__ bool elect_one() {
    uint32_t pred;
    asm volatile("{\n\t.reg .pred p;\n\telect.sync _|p, 0xFFFFFFFF;\n\t"
                 "selp.b32 %0, 1, 0, p;\n\t}" : "=r"(pred));
    return pred != 0;
}
__device__ __forceinline__ void mbar_init(uint32_t addr, uint32_t cnt) {
    asm volatile("mbarrier.init.shared.b64 [%0], %1;" :: "r"(addr), "r"(cnt)
                 : "memory");
}
__device__ __forceinline__ void mbar_wait(uint32_t addr, uint32_t phase) {
    asm volatile(
        "{\n\t.reg .pred P;\n\t"
        "W%=:\n\t"
        "mbarrier.try_wait.parity.acquire.cta.shared::cta.b64 P, [%0], %1, 0x989680;\n\t"
        "@!P bra W%=;\n\t}"
        :: "r"(addr), "r"(phase) : "memory");
}
__device__ __forceinline__ void tmem_alloc(uint32_t dst_smem, uint32_t ncols) {
    asm volatile("tcgen05.alloc.cta_group::1.sync.aligned.shared::cta.b32 [%0], %1;"
                 :: "r"(dst_smem), "r"(ncols) : "memory");
}
__device__ __forceinline__ void tmem_relinquish() {
    asm volatile("tcgen05.relinquish_alloc_permit.cta_group::1.sync.aligned;");
}
__device__ __forceinline__ void tmem_dealloc(uint32_t base, uint32_t ncols) {
    asm volatile("tcgen05.dealloc.cta_group::1.sync.aligned.b32 %0, %1;"
                 :: "r"(base), "r"(ncols));
}
__device__ __forceinline__ void fence_proxy_async_sc() {
    asm volatile("fence.proxy.async.shared::cta;" ::: "memory");
}
__device__ __forceinline__ void tc_fence_after() {
    asm volatile("tcgen05.fence::after_thread_sync;" ::: "memory");
}
__device__ __forceinline__ void tc_fence_before() {
    asm volatile("tcgen05.fence::before_thread_sync;" ::: "memory");
}
__device__ __forceinline__ void tc_wait_ld() {
    asm volatile("tcgen05.wait::ld.sync.aligned;" ::: "memory");
}
__device__ __forceinline__ void tc_commit(uint32_t mbar) {
    asm volatile(
        "tcgen05.commit.cta_group::1.mbarrier::arrive::one.shared::cluster.b64 [%0];"
        :: "r"(mbar) : "memory");
}
__device__ __forceinline__ void mma_ss_bf16(uint32_t d, uint64_t ad, uint64_t bd,
                                            uint32_t idesc, uint32_t en) {
    asm volatile(
        "{\n\t.reg .pred p;\n\tsetp.ne.u32 p, %4, 0;\n\t"
        "tcgen05.mma.cta_group::1.kind::f16 [%0], %1, %2, %3, {%5,%5,%5,%5}, p;\n\t}"
        :: "r"(d), "l"(ad), "l"(bd), "r"(idesc), "r"(en), "r"(0u) : "memory");
}
__device__ __forceinline__ void ldtm_x32(uint32_t* r, uint32_t addr) {
    asm volatile(
        "tcgen05.ld.sync.aligned.32x32b.x32.b32 "
        "{%0, %1, %2, %3, %4, %5, %6, %7, "
        " %8, %9, %10, %11, %12, %13, %14, %15, "
        " %16, %17, %18, %19, %20, %21, %22, %23, "
        " %24, %25, %26, %27, %28, %29, %30, %31}, [%32];"
        : "=r"(r[0]),  "=r"(r[1]),  "=r"(r[2]),  "=r"(r[3]),
          "=r"(r[4]),  "=r"(r[5]),  "=r"(r[6]),  "=r"(r[7]),
          "=r"(r[8]),  "=r"(r[9]),  "=r"(r[10]), "=r"(r[11]),
          "=r"(r[12]), "=r"(r[13]), "=r"(r[14]), "=r"(r[15]),
          "=r"(r[16]), "=r"(r[17]), "=r"(r[18]), "=r"(r[19]),
          "=r"(r[20]), "=r"(r[21]), "=r"(r[22]), "=r"(r[23]),
          "=r"(r[24]), "=r"(r[25]), "=r"(r[26]), "=r"(r[27]),
          "=r"(r[28]), "=r"(r[29]), "=r"(r[30]), "=r"(r[31])
        : "r"(addr));
}
__device__ __forceinline__ uint64_t mk_desc(uint32_t addr) {
    const uint64_t base = (2ull << 61) | (1ull << 46) | (64ull << 32) | (1ull << 16);
    return base | ((addr >> 4) & 0x3FFF);
}
#else
__device__ __forceinline__ unsigned long long pack_dup(float a) {
    unsigned long long r;
    asm("mov.b64 %0, {%1, %1};" : "=l"(r) : "f"(a));
    return r;
}
__device__ __forceinline__ void fma2(unsigned long long& acc,
                                     unsigned long long a,
                                     unsigned long long b) {
    asm("fma.rn.f32x2 %0, %1, %2, %0;" : "+l"(acc) : "l"(a), "l"(b));
}
__device__ __forceinline__ float2 unpack2(unsigned long long v) {
    float lo, hi;
    asm("mov.b64 {%0, %1}, %2;" : "=f"(lo), "=f"(hi) : "l"(v));
    return make_float2(lo, hi);
}
#endif

// ---------------- prep: weight split helper ----------------
template <int CIN, int COUT, int BK, int KCH>
__device__ __forceinline__ void wsplit_one(const float* __restrict__ W, int idx,
                                           int whbase, int wfbase) {
    int ci   = idx & 63;
    int rowI = idx >> 6;
    int co   = rowI % COUT;
    int c    = rowI / COUT;
    int off = c / KCH, kc = c % KCH;
    int cig = kc * 64 + ci;
    float v = 0.f;
    if (ci < BK) v = W[((size_t)(off * CIN + cig)) * COUT + co];
    __nv_bfloat16 h = __float2bfloat16(v);
    __nv_bfloat16 l = __float2bfloat16(v - __bfloat162float(h));
    int dst = rowI * 64 + ((((ci >> 3) ^ (co & 7)) << 3) | (ci & 7));
    g_Wh[whbase + dst] = h;
    g_Wl[whbase + dst] = l;
    if (ci < BK)
        g_Wf[wfbase + ((size_t)c * BK + ci) * COUT + co] = v;
}

// prep0: map init + all weight splits (launch #1)
__global__ void prep0_kernel(const float* __restrict__ W0,
                             const float* __restrict__ W1,
                             const float* __restrict__ W2) {
    int i = blockIdx.x * 256 + threadIdx.x;         // grid covers NVOX
    if (i < NVOX) g_map[i] = -1;
    if (i < 110592)      wsplit_one<16, 64, 16, 1>(W0, i, WH0, WF0);
    else if (i < 331776) wsplit_one<64, 128, 64, 1>(W1, i - 110592, WH1, WF1);
    else if (i < 552960) wsplit_one<128, 64, 64, 2>(W2, i - 331776, WH2, WF2);
}

// prep1: scatter map + feature split (launch #2)
__global__ void prep1_kernel(const int* __restrict__ idxs,
                             const float* __restrict__ f) {
    int i = blockIdx.x * 256 + threadIdx.x;         // grid covers NPTS*16
    if (i < NPTS) {
        int b = idxs[4*i+0], z = idxs[4*i+1], y = idxs[4*i+2], x = idxs[4*i+3];
        g_map[((b*DD + z)*DD + y)*DD + x] = i;
    }
    float v = f[i];
    __nv_bfloat16 h = __float2bfloat16(v);
    g_fh[i] = h;
    g_fl[i] = __float2bfloat16(v - __bfloat162float(h));
}

// launch #3
__global__ void build_nbr_kernel(const int* __restrict__ idxs) {
    int tid = blockIdx.x * 256 + threadIdx.x;
    int k = tid / NPTS;
    int n = tid - k * NPTS;
    int b = idxs[4*n+0], z = idxs[4*n+1], y = idxs[4*n+2], x = idxs[4*n+3];
    int zz = z + k/9 - 1, yy = y + (k/3)%3 - 1, xx = x + (k%3) - 1;
    int r = -1;
    if ((unsigned)zz < DD && (unsigned)yy < DD && (unsigned)xx < DD)
        r = g_map[((b*DD + zz)*DD + yy)*DD + xx];
    g_nbr[tid] = r;
}

// ---------------- conv: tcgen05 path OR scalar fallback ----------------
// grid = NBLK / TG; each CTA owns TG tiles (TG*COUT = 256 TMEM cols).
template <int CIN, int COUT, int BK, int KCH, int TG>
__global__ void __launch_bounds__(256)
conv_kernel(const float* __restrict__ featF,
            const float* __restrict__ bias,
            int whbase, int wfbase) {
#if HAS_TCGEN05
    constexpr int C     = 27 * KCH;
    constexpr int TOT   = C * TG;
    constexpr int NK    = BK / 16;
    constexpr int CSEG  = BK / 8;
    constexpr int ATILE = 128 * 128;
    constexpr int ASTG  = 2 * ATILE;
    constexpr int BTILE = COUT * 128;
    constexpr int CPW   = COUT / 2;
    constexpr uint32_t IDESC =
        (1u << 4) | (1u << 7) | (1u << 10) | ((COUT / 8) << 17) | (8u << 24);

    extern __shared__ __align__(16) char dsm_raw[];
    __shared__ __align__(8) unsigned long long s_mbar[2];
    __shared__ uint32_t s_tmem;
    __shared__ float sP[4][128], sQ[4][128];

    char* smp = (char*)((((uintptr_t)dsm_raw) + 1023) & ~(uintptr_t)1023);
    const uint32_t smu = smem_u32(smp);
    const uint32_t aBase = smu;
    const uint32_t bBase = smu + 2 * ASTG;

    const int t    = threadIdx.x;
    const int wid  = t >> 5;
    const int lane = t & 31;

    if (wid == 0) {
        tmem_alloc(smem_u32(&s_tmem), TG * COUT);   // 256 cols: 2 CTAs/SM fit
        tmem_relinquish();
    }
    if (t == 0) { mbar_init(smem_u32(&s_mbar[0]), 1);
                  mbar_init(smem_u32(&s_mbar[1]), 1); }
    __syncthreads();
    const uint32_t tmem = s_tmem;
    const uint32_t mba[2] = { smem_u32(&s_mbar[0]), smem_u32(&s_mbar[1]) };

    const int tileBase = blockIdx.x * TG;
    const int r    = t >> 1;
    const int half = t & 1;
    const __nv_bfloat16* fp = half ? g_fl : g_fh;

    uint32_t ph[2]   = {0u, 0u};
    bool     pend[2] = {false, false};

    float4 v[8];
    const float4 z4 = make_float4(0.f, 0.f, 0.f, 0.f);

    // register preload of iteration it
    auto preload = [&](int it) {
        const int c  = it / TG;
        const int j  = it - c * TG;
        const int off = c / KCH, kc = c - off * KCH;
        const int nb = g_nbr[off * NPTS + (tileBase + j) * BM + r];
        const float4* src =
            (const float4*)(fp + (size_t)(nb < 0 ? 0 : nb) * CIN + kc * 64);
        #pragma unroll
        for (int s = 0; s < 8; ++s)
            v[s] = (nb >= 0 && s < CSEG) ? src[s] : z4;
    };

    preload(0);

    #pragma unroll 1
    for (int it = 0; it < TOT; ++it) {
        const int c   = it / TG;
        const int j   = it - c * TG;
        const int buf = it & 1;

        if (j == 0) {
            // drain everything, then refresh B for this chunk
            #pragma unroll
            for (int b = 0; b < 2; ++b)
                if (pend[b]) { mbar_wait(mba[b], ph[b]); ph[b] ^= 1;
                               pend[b] = false; }
            const float4* sh = (const float4*)(g_Wh + whbase +
                                               (size_t)c * COUT * 64);
            const float4* sl = (const float4*)(g_Wl + whbase +
                                               (size_t)c * COUT * 64);
            float4* dh = (float4*)(smp + 2 * ASTG);
            float4* dl = (float4*)(smp + 2 * ASTG + BTILE);
            #pragma unroll
            for (int i = 0; i < BTILE / 16 / 256; ++i) {
                dh[t + i * 256] = sh[t + i * 256];
                dl[t + i * 256] = sl[t + i * 256];
            }
        }
        if (pend[buf]) { mbar_wait(mba[buf], ph[buf]); ph[buf] ^= 1;
                         pend[buf] = false; }

        // store staged registers into A buffer
        {
            float4* dA = (float4*)(smp + buf * ASTG + half * ATILE + r * 128);
            #pragma unroll
            for (int s = 0; s < 8; ++s)
                dA[s ^ (r & 7)] = v[s];
        }
        fence_proxy_async_sc();
        __syncthreads();

        // issue next iteration's global loads NOW (latency hidden under MMA)
        if (it + 1 < TOT) preload(it + 1);

        if (wid == 0) {
            tc_fence_after();
            if (elect_one()) {
                const uint32_t ab = aBase + buf * ASTG;
                uint64_t dAh = mk_desc(ab);
                uint64_t dAl = mk_desc(ab + ATILE);
                uint64_t dBh = mk_desc(bBase);
                uint64_t dBl = mk_desc(bBase + BTILE);
                const uint32_t dTm = tmem + (uint32_t)(j * COUT);
                #pragma unroll
                for (int ks = 0; ks < NK; ++ks)
                    mma_ss_bf16(dTm, dAh + ks * 2, dBh + ks * 2, IDESC,
                                (c == 0 && ks == 0) ? 0u : 1u);
                #pragma unroll
                for (int ks = 0; ks < NK; ++ks)
                    mma_ss_bf16(dTm, dAh + ks * 2, dBl + ks * 2, IDESC, 1u);
                #pragma unroll
                for (int ks = 0; ks < NK; ++ks)
                    mma_ss_bf16(dTm, dAl + ks * 2, dBh + ks * 2, IDESC, 1u);
                tc_commit(mba[buf]);
            }
        }
        pend[buf] = true;
    }

    #pragma unroll
    for (int b = 0; b < 2; ++b)
        if (pend[b]) { mbar_wait(mba[b], ph[b]); ph[b] ^= 1; pend[b] = false; }
    tc_fence_after();

    // ---------------- epilogue ----------------
    const int grp     = wid >> 2;
    const int rw      = wid & 3;
    const int colBase = grp * CPW;

    for (int j = 0; j < TG; ++j) {
        const int tile = tileBase + j;
        const int row  = tile * BM + rw * 32 + lane;
        #pragma unroll
        for (int p = 0; p < CPW / 32; ++p) {
            uint32_t dr[32];
            ldtm_x32(dr, tmem + (uint32_t)(j * COUT + colBase + p * 32));
            tc_wait_ld();
            #pragma unroll
            for (int jj = 0; jj < 32; jj += 4) {
                float y[4];
                #pragma unroll
                for (int q = 0; q < 4; ++q) {
                    int col = colBase + p * 32 + jj + q;
                    y[q] = __uint_as_float(dr[jj + q]) + __ldg(bias + col);
                    float s = y[q], qq = y[q] * y[q];
                    #pragma unroll
                    for (int o = 16; o; o >>= 1) {
                        s  += __shfl_xor_sync(0xffffffffu, s, o);
                        qq += __shfl_xor_sync(0xffffffffu, qq, o);
                    }
                    if (lane == (col & 31)) {
                        sP[rw][col] = s;
                        sQ[rw][col] = qq;
                    }
                }
                *(float4*)(&g_conv[(size_t)row * COUT + colBase + p * 32 + jj]) =
                    make_float4(y[0], y[1], y[2], y[3]);
            }
        }
        __syncthreads();
        if (t < COUT) {
            g_part[(size_t)tile * COUT + t] =
                sP[0][t] + sP[1][t] + sP[2][t] + sP[3][t];
            g_partsq[(size_t)tile * COUT + t] =
                sQ[0][t] + sQ[1][t] + sQ[2][t] + sQ[3][t];
        }
        __syncthreads();
    }
    tc_fence_before();
    __syncthreads();
    if (wid == 0) tmem_dealloc(tmem, TG * COUT);

#else  // ------------------- scalar FFMA fallback (no tcgen05) -------------
    constexpr int TN   = COUT / 16;
    constexpr int SEGS = BK / 4;

    extern __shared__ __align__(16) float sm[];
    float* As = sm;
    float* Bs = sm + BK * BM;
    __shared__ int sN[BM];

    const int t  = threadIdx.x;
    const int tr = t >> 4;
    const int tc = t & 15;

    for (int tile = blockIdx.x * TG; tile < (blockIdx.x + 1) * TG; ++tile) {
        const int rowBase = tile * BM;

        unsigned long long acc[8][TN/2];
        #pragma unroll
        for (int i = 0; i < 8; i++)
            #pragma unroll
            for (int j = 0; j < TN/2; j++) acc[i][j] = 0ull;

        for (int k = 0; k < 27; k++) {
            __syncthreads();
            if (t < BM) sN[t] = g_nbr[k * NPTS + rowBase + t];
            __syncthreads();
            #pragma unroll
            for (int kc = 0; kc < KCH; kc++) {
                if (kc) __syncthreads();
                #pragma unroll
                for (int f = t; f < BM * SEGS; f += 256) {
                    int row = f / SEGS;
                    int seg = f - row * SEGS;
                    int nb  = sN[row];
                    float4 v = make_float4(0.f, 0.f, 0.f, 0.f);
                    if (nb >= 0)
                        v = *reinterpret_cast<const float4*>(
                            featF + (size_t)nb * CIN + kc * BK + seg * 4);
                    int rs = row ^ ((seg & 3) << 3);
                    As[(seg*4+0)*BM + rs] = v.x;
                    As[(seg*4+1)*BM + rs] = v.y;
                    As[(seg*4+2)*BM + rs] = v.z;
                    As[(seg*4+3)*BM + rs] = v.w;
                }
                const float4* Wk = (const float4*)(
                    g_Wf + wfbase + ((size_t)(k * KCH + kc)) * BK * COUT);
                #pragma unroll
                for (int f = t; f < BK * COUT / 4; f += 256)
                    reinterpret_cast<float4*>(Bs)[f] = Wk[f];
                __syncthreads();
                #pragma unroll 8
                for (int kk = 0; kk < BK; kk++) {
                    int rbase = (tr * 8) ^ (((kk >> 2) & 3) << 3);
                    float4 a0 = *reinterpret_cast<const float4*>(&As[kk*BM + rbase]);
                    float4 a1 = *reinterpret_cast<const float4*>(&As[kk*BM + rbase + 4]);
                    unsigned long long ad[8];
                    ad[0] = pack_dup(a0.x); ad[1] = pack_dup(a0.y);
                    ad[2] = pack_dup(a0.z); ad[3] = pack_dup(a0.w);
                    ad[4] = pack_dup(a1.x); ad[5] = pack_dup(a1.y);
                    ad[6] = pack_dup(a1.z); ad[7] = pack_dup(a1.w);
                    unsigned long long bb[TN/2];
                    const ulonglong2* bp = reinterpret_cast<const ulonglong2*>(
                        &Bs[kk * COUT + tc * TN]);
                    {
                        ulonglong2 b0 = bp[0];
                        bb[0] = b0.x; bb[1] = b0.y;
                        if constexpr (TN == 8) {
                            ulonglong2 b1 = bp[1];
                            bb[2] = b1.x; bb[3] = b1.y;
                        }
                    }
                    #pragma unroll
                    for (int i = 0; i < 8; i++)
                        #pragma unroll
                        for (int j = 0; j < TN/2; j++)
                            fma2(acc[i][j], ad[i], bb[j]);
                }
            }
        }

        float bv[TN];
        #pragma unroll
        for (int j = 0; j < TN; j++) bv[j] = bias[tc * TN + j];
        float cs[TN], cq[TN];
        #pragma unroll
        for (int j = 0; j < TN; j++) { cs[j] = 0.f; cq[j] = 0.f; }

        #pragma unroll
        for (int i = 0; i < 8; i++) {
            float yv[TN];
            #pragma unroll
            for (int j = 0; j < TN/2; j++) {
                float2 p = unpack2(acc[i][j]);
                yv[2*j]   = p.x + bv[2*j];
                yv[2*j+1] = p.y + bv[2*j+1];
            }
            #pragma unroll
            for (int j = 0; j < TN; j++) { cs[j] += yv[j]; cq[j] += yv[j]*yv[j]; }
            int row = rowBase + tr * 8 + i;
            #pragma unroll
            for (int j = 0; j < TN; j += 4) {
                float4 o = make_float4(yv[j], yv[j+1], yv[j+2], yv[j+3]);
                *reinterpret_cast<float4*>(
                    &g_conv[(size_t)row * COUT + tc * TN + j]) = o;
            }
        }

        __syncthreads();
        #pragma unroll
        for (int j = 0; j < TN; j++) As[tr * COUT + tc * TN + j] = cs[j];
        __syncthreads();
        if (t < COUT) {
            float s = 0.f;
            #pragma unroll
            for (int rr = 0; rr < 16; rr++) s += As[rr * COUT + t];
            g_part[(size_t)tile * COUT + t] = s;
        }
        __syncthreads();
        #pragma unroll
        for (int j = 0; j < TN; j++) As[tr * COUT + tc * TN + j] = cq[j];
        __syncthreads();
        if (t < COUT) {
            float s = 0.f;
            #pragma unroll
            for (int rr = 0; rr < 16; rr++) s += As[rr * COUT + t];
            g_partsq[(size_t)tile * COUT + t] = s;
        }
        __syncthreads();
    }
#endif
}

// ---------------- BN statistics ----------------
__global__ void bn_reduce_kernel(const float* __restrict__ gamma,
                                 const float* __restrict__ beta, int cout) {
    __shared__ float ss[256], sq[256];
    int c = blockIdx.x;
    int t = threadIdx.x;
    float s = 0.f, q = 0.f;
    for (int b = t; b < NBLK; b += 256) {
        s += g_part[b * cout + c];
        q += g_partsq[b * cout + c];
    }
    ss[t] = s; sq[t] = q;
    __syncthreads();
    for (int o = 128; o > 0; o >>= 1) {
        if (t < o) { ss[t] += ss[t + o]; sq[t] += sq[t + o]; }
        __syncthreads();
    }
    if (t == 0) {
        float mean = ss[0] * INVN;
        float var  = sq[0] * INVN - mean * mean;
        float sc   = gamma[c] * rsqrtf(var + BN_EPS);
        g_scale[c] = sc;
        g_shift[c] = beta[c] - mean * sc;
    }
}

// ---------------- BN apply + ReLU -> bf16 hi/lo (fp32 only for fallback) ---
template <int COUT>
__global__ void bnrelu_kernel() {
    int i = blockIdx.x * 256 + threadIdx.x;
    int c = i & (COUT - 1);
    float v = fmaf(g_conv[i], g_scale[c], g_shift[c]);
    v = v > 0.f ? v : 0.f;
#if !HAS_TCGEN05
    g_feat[i] = v;
#endif
    __nv_bfloat16 h = __float2bfloat16(v);
    g_fh[i] = h;
    g_fl[i] = __float2bfloat16(v - __bfloat162float(h));
}

// ---------------- final dense scatter [B,64,12,12,12] ----------------
__global__ void final_out_kernel(float* __restrict__ out) {
    int idx = blockIdx.x * 256 + threadIdx.x;
    int lin = idx % VOLPB;
    int bc  = idx / VOLPB;
    int c = bc & 63;
    int b = bc >> 6;
    int row = g_map[b * VOLPB + lin];
    float v = 0.f;
    if (row >= 0) {
        float y = fmaf(g_conv[(size_t)row * 64 + c], g_scale[c], g_shift[c]);
        v = y > 0.f ? y : 0.f;
    }
    out[idx] = v;
}

// ---------------- launch ----------------
extern "C" void kernel_launch(void* const* d_in, const int* in_sizes, int n_in,
                              void* d_out, int out_size) {
    (void)in_sizes; (void)out_size;
    int base = (n_in >= 15) ? 3 : 2;
    const float* features = (const float*)d_in[0];
    const int*   indices  = (const int*)d_in[1];
    const float* W0  = (const float*)d_in[base + 0];
    const float* b0  = (const float*)d_in[base + 1];
    const float* ga0 = (const float*)d_in[base + 2];
    const float* be0 = (const float*)d_in[base + 3];
    const float* W1  = (const float*)d_in[base + 4];
    const float* b1  = (const float*)d_in[base + 5];
    const float* ga1 = (const float*)d_in[base + 6];
    const float* be1 = (const float*)d_in[base + 7];
    const float* W2  = (const float*)d_in[base + 8];
    const float* b2  = (const float*)d_in[base + 9];
    const float* ga2 = (const float*)d_in[base + 10];
    const float* be2 = (const float*)d_in[base + 11];
    float* out = (float*)d_out;

    float* featp = nullptr;
    cudaGetSymbolAddress((void**)&featp, g_feat);

    constexpr int SM64  = 4 * 16384 + 2 * 64  * 128 + 1024;  // 82944
    constexpr int SM128 = 4 * 16384 + 2 * 128 * 128 + 1024;  // 99328
    cudaFuncSetAttribute(conv_kernel<16, 64, 16, 1, 4>,
                         cudaFuncAttributeMaxDynamicSharedMemorySize, SM64);
    cudaFuncSetAttribute(conv_kernel<64, 128, 64, 1, 2>,
                         cudaFuncAttributeMaxDynamicSharedMemorySize, SM128);
    cudaFuncSetAttribute(conv_kernel<128, 64, 64, 2, 4>,
                         cudaFuncAttributeMaxDynamicSharedMemorySize, SM64);

    prep0_kernel<<<NVOX / 256, 256>>>(W0, W1, W2);            // 1
    prep1_kernel<<<NPTS * 16 / 256, 256>>>(indices, features);// 2
    build_nbr_kernel<<<27 * NPTS / 256, 256>>>(indices);      // 3

    // layer 0: 16 -> 64 (TG=4 -> 864 CTAs)      launch #4 (profiled slot)
    conv_kernel<16, 64, 16, 1, 4><<<NBLK / 4, 256, SM64>>>(features, b0,
                                                           WH0, WF0);
    bn_reduce_kernel<<<64, 256>>>(ga0, be0, 64);
    bnrelu_kernel<64><<<NPTS * 64 / 256, 256>>>();

    // layer 1: 64 -> 128 (TG=2 -> 1728 CTAs)
    conv_kernel<64, 128, 64, 1, 2><<<NBLK / 2, 256, SM128>>>(featp, b1,
                                                             WH1, WF1);
    bn_reduce_kernel<<<128, 256>>>(ga1, be1, 128);
    bnrelu_kernel<128><<<NPTS * 128 / 256, 256>>>();

    // layer 2: 128 -> 64 (TG=4 -> 864 CTAs)
    conv_kernel<128, 64, 64, 2, 4><<<NBLK / 4, 256, SM64>>>(featp, b2,
                                                            WH2, WF2);
    bn_reduce_kernel<<<64, 256>>>(ga2, be2, 64);

    final_out_kernel<<<(BATCH * 64 * VOLPB) / 256, 256>>>(out);
}

// round 9
// speedup vs baseline: 3.2653x; 1.4600x over previous
#include <cuda_runtime.h>
#include <cuda_bf16.h>
#include <cstdint>

#define DD     12
#define VOLPB  1728
#define BATCH  512
#define NPTS   442368
#define NVOX   884736
#define BM     128
#define NBLK   3456
#define INVN   (1.0f/442368.0f)
#define BN_EPS 1e-5f

#define WH0 0
#define WH1 110592
#define WH2 331776
#define WHTOT 552960
#define WF0 0
#define WF1 27648
#define WF2 248832
#define WFTOT 470016

#if defined(__CUDA_ARCH__) && (defined(__CUDA_ARCH_FEAT_SM103_ALL) || \
    defined(__CUDA_ARCH_FEAT_SM100_ALL) || defined(__CUDA_ARCH_FEAT_SM101_ALL))
#define HAS_TCGEN05 1
#else
#define HAS_TCGEN05 0
#endif

// ---------------- device scratch ----------------
__device__ __align__(256) int            g_map[NVOX];
__device__ __align__(256) int            g_nbr[27 * NPTS];
__device__ __align__(256) float          g_feat[(size_t)NPTS * 128];
__device__ __align__(256) __nv_bfloat16  g_fh[(size_t)NPTS * 128];
__device__ __align__(256) __nv_bfloat16  g_fl[(size_t)NPTS * 128];
__device__ __align__(256) float          g_conv[(size_t)NPTS * 128];
__device__ __align__(256) __nv_bfloat16  g_Wh[WHTOT];
__device__ __align__(256) __nv_bfloat16  g_Wl[WHTOT];
__device__ __align__(256) float          g_Wf[WFTOT];
__device__ __align__(256) float          g_part[NBLK * 128];
__device__ __align__(256) float          g_partsq[NBLK * 128];
__device__ __align__(256) float          g_scale[128];
__device__ __align__(256) float          g_shift[128];

// ---------------- generic helpers ----------------
__device__ __forceinline__ uint32_t smem_u32(const void* p) {
    uint32_t a;
    asm("{ .reg .u64 t; cvta.to.shared.u64 t, %1; cvt.u32.u64 %0, t; }"
        : "=r"(a) : "l"(p));
    return a;
}

#if HAS_TCGEN05
__device__ __forceinline__ bool elect_one() {
    uint32_t pred;
    asm volatile("{\n\t.reg .pred p;\n\telect.sync _|p, 0xFFFFFFFF;\n\t"
                 "selp.b32 %0, 1, 0, p;\n\t}" : "=r"(pred));
    return pred != 0;
}
__device__ __forceinline__ void mbar_init(uint32_t addr, uint32_t cnt) {
    asm volatile("mbarrier.init.shared.b64 [%0], %1;" :: "r"(addr), "r"(cnt)
                 : "memory");
}
__device__ __forceinline__ void mbar_wait(uint32_t addr, uint32_t phase) {
    asm volatile(
        "{\n\t.reg .pred P;\n\t"
        "W%=:\n\t"
        "mbarrier.try_wait.parity.acquire.cta.shared::cta.b64 P, [%0], %1, 0x989680;\n\t"
        "@!P bra W%=;\n\t}"
        :: "r"(addr), "r"(phase) : "memory");
}
__device__ __forceinline__ void tmem_alloc(uint32_t dst_smem, uint32_t ncols) {
    asm volatile("tcgen05.alloc.cta_group::1.sync.aligned.shared::cta.b32 [%0], %1;"
                 :: "r"(dst_smem), "r"(ncols) : "memory");
}
__device__ __forceinline__ void tmem_relinquish() {
    asm volatile("tcgen05.relinquish_alloc_permit.cta_group::1.sync.aligned;");
}
__device__ __forceinline__ void tmem_dealloc(uint32_t base, uint32_t ncols) {
    asm volatile("tcgen05.dealloc.cta_group::1.sync.aligned.b32 %0, %1;"
                 :: "r"(base), "r"(ncols));
}
__device__ __forceinline__ void fence_proxy_async_sc() {
    asm volatile("fence.proxy.async.shared::cta;" ::: "memory");
}
__device__ __forceinline__ void tc_fence_after() {
    asm volatile("tcgen05.fence::after_thread_sync;" ::: "memory");
}
__device__ __forceinline__ void tc_fence_before() {
    asm volatile("tcgen05.fence::before_thread_sync;" ::: "memory");
}
__device__ __forceinline__ void tc_wait_ld() {
    asm volatile("tcgen05.wait::ld.sync.aligned;" ::: "memory");
}
__device__ __forceinline__ void tc_commit(uint32_t mbar) {
    asm volatile(
        "tcgen05.commit.cta_group::1.mbarrier::arrive::one.shared::cluster.b64 [%0];"
        :: "r"(mbar) : "memory");
}
__device__ __forceinline__ void mma_ss_bf16(uint32_t d, uint64_t ad, uint64_t bd,
                                            uint32_t idesc, uint32_t en) {
    asm volatile(
        "{\n\t.reg .pred p;\n\tsetp.ne.u32 p, %4, 0;\n\t"
        "tcgen05.mma.cta_group::1.kind::f16 [%0], %1, %2, %3, {%5,%5,%5,%5}, p;\n\t}"
        :: "r"(d), "l"(ad), "l"(bd), "r"(idesc), "r"(en), "r"(0u) : "memory");
}
__device__ __forceinline__ void ldtm_x32(uint32_t* r, uint32_t addr) {
    asm volatile(
        "tcgen05.ld.sync.aligned.32x32b.x32.b32 "
        "{%0, %1, %2, %3, %4, %5, %6, %7, "
        " %8, %9, %10, %11, %12, %13, %14, %15, "
        " %16, %17, %18, %19, %20, %21, %22, %23, "
        " %24, %25, %26, %27, %28, %29, %30, %31}, [%32];"
        : "=r"(r[0]),  "=r"(r[1]),  "=r"(r[2]),  "=r"(r[3]),
          "=r"(r[4]),  "=r"(r[5]),  "=r"(r[6]),  "=r"(r[7]),
          "=r"(r[8]),  "=r"(r[9]),  "=r"(r[10]), "=r"(r[11]),
          "=r"(r[12]), "=r"(r[13]), "=r"(r[14]), "=r"(r[15]),
          "=r"(r[16]), "=r"(r[17]), "=r"(r[18]), "=r"(r[19]),
          "=r"(r[20]), "=r"(r[21]), "=r"(r[22]), "=r"(r[23]),
          "=r"(r[24]), "=r"(r[25]), "=r"(r[26]), "=r"(r[27]),
          "=r"(r[28]), "=r"(r[29]), "=r"(r[30]), "=r"(r[31])
        : "r"(addr));
}
__device__ __forceinline__ uint64_t mk_desc(uint32_t addr) {
    const uint64_t base = (2ull << 61) | (1ull << 46) | (64ull << 32) | (1ull << 16);
    return base | ((addr >> 4) & 0x3FFF);
}
__device__ __forceinline__ void cp16(uint32_t dst, const void* src, int srcsz) {
    asm volatile("cp.async.cg.shared.global [%0], [%1], 16, %2;"
                 :: "r"(dst), "l"(src), "r"(srcsz) : "memory");
}
__device__ __forceinline__ void cp_commit() {
    asm volatile("cp.async.commit_group;" ::: "memory");
}
__device__ __forceinline__ void cp_wait1() {
    asm volatile("cp.async.wait_group 1;" ::: "memory");
}
__device__ __forceinline__ void cp_wait0() {
    asm volatile("cp.async.wait_group 0;" ::: "memory");
}
#else
__device__ __forceinline__ unsigned long long pack_dup(float a) {
    unsigned long long r;
    asm("mov.b64 %0, {%1, %1};" : "=l"(r) : "f"(a));
    return r;
}
__device__ __forceinline__ void fma2(unsigned long long& acc,
                                     unsigned long long a,
                                     unsigned long long b) {
    asm("fma.rn.f32x2 %0, %1, %2, %0;" : "+l"(acc) : "l"(a), "l"(b));
}
__device__ __forceinline__ float2 unpack2(unsigned long long v) {
    float lo, hi;
    asm("mov.b64 {%0, %1}, %2;" : "=f"(lo), "=f"(hi) : "l"(v));
    return make_float2(lo, hi);
}
#endif

// ---------------- prep ----------------
template <int CIN, int COUT, int BK, int KCH>
__device__ __forceinline__ void wsplit_one(const float* __restrict__ W, int idx,
                                           int whbase, int wfbase) {
    int ci   = idx & 63;
    int rowI = idx >> 6;
    int co   = rowI % COUT;
    int c    = rowI / COUT;
    int off = c / KCH, kc = c % KCH;
    int cig = kc * 64 + ci;
    float v = 0.f;
    if (ci < BK) v = W[((size_t)(off * CIN + cig)) * COUT + co];
    __nv_bfloat16 h = __float2bfloat16(v);
    __nv_bfloat16 l = __float2bfloat16(v - __bfloat162float(h));
    int dst = rowI * 64 + ((((ci >> 3) ^ (co & 7)) << 3) | (ci & 7));
    g_Wh[whbase + dst] = h;
    g_Wl[whbase + dst] = l;
    if (ci < BK)
        g_Wf[wfbase + ((size_t)c * BK + ci) * COUT + co] = v;
}

__global__ void prep0_kernel(const float* __restrict__ W0,
                             const float* __restrict__ W1,
                             const float* __restrict__ W2) {
    int i = blockIdx.x * 256 + threadIdx.x;
    if (i < NVOX) g_map[i] = -1;
    if (i < 110592)      wsplit_one<16, 64, 16, 1>(W0, i, WH0, WF0);
    else if (i < 331776) wsplit_one<64, 128, 64, 1>(W1, i - 110592, WH1, WF1);
    else if (i < 552960) wsplit_one<128, 64, 64, 2>(W2, i - 331776, WH2, WF2);
}

__global__ void prep1_kernel(const int* __restrict__ idxs,
                             const float* __restrict__ f) {
    int i = blockIdx.x * 256 + threadIdx.x;
    if (i < NPTS) {
        int b = idxs[4*i+0], z = idxs[4*i+1], y = idxs[4*i+2], x = idxs[4*i+3];
        g_map[((b*DD + z)*DD + y)*DD + x] = i;
    }
    float v = f[i];
    __nv_bfloat16 h = __float2bfloat16(v);
    g_fh[i] = h;
    g_fl[i] = __float2bfloat16(v - __bfloat162float(h));
}

__global__ void build_nbr_kernel(const int* __restrict__ idxs) {
    int tid = blockIdx.x * 256 + threadIdx.x;
    int k = tid / NPTS;
    int n = tid - k * NPTS;
    int b = idxs[4*n+0], z = idxs[4*n+1], y = idxs[4*n+2], x = idxs[4*n+3];
    int zz = z + k/9 - 1, yy = y + (k/3)%3 - 1, xx = x + (k%3) - 1;
    int r = -1;
    if ((unsigned)zz < DD && (unsigned)yy < DD && (unsigned)xx < DD)
        r = g_map[((b*DD + zz)*DD + yy)*DD + xx];
    g_nbr[tid] = r;
}

// ---------------- conv ----------------
template <int CIN, int COUT, int BK, int KCH, int TG>
__global__ void __launch_bounds__(256)
conv_kernel(const float* __restrict__ featF,
            const float* __restrict__ bias,
            int whbase, int wfbase) {
#if HAS_TCGEN05
    constexpr int C     = 27 * KCH;
    constexpr int TOT   = C * TG;
    constexpr int NK    = BK / 16;
    constexpr int CSEG  = BK / 8;
    constexpr int ATILE = 128 * 128;
    constexpr int ASTG  = 2 * ATILE;
    constexpr int BTILE = COUT * 128;
    constexpr int CPW   = COUT / 2;
    constexpr uint32_t IDESC =
        (1u << 4) | (1u << 7) | (1u << 10) | ((COUT / 8) << 17) | (8u << 24);

    extern __shared__ __align__(16) char dsm_raw[];
    __shared__ __align__(8) unsigned long long s_mbar[2];
    __shared__ uint32_t s_tmem;
    __shared__ float sP[4][128], sQ[4][128];

    char* smp = (char*)((((uintptr_t)dsm_raw) + 1023) & ~(uintptr_t)1023);
    const uint32_t smu = smem_u32(smp);
    const uint32_t aBase = smu;
    const uint32_t bBase = smu + 2 * ASTG;

    const int t    = threadIdx.x;
    const int wid  = t >> 5;
    const int lane = t & 31;

    if (wid == 0) {
        tmem_alloc(smem_u32(&s_tmem), TG * COUT);
        tmem_relinquish();
    }
    if (t == 0) { mbar_init(smem_u32(&s_mbar[0]), 1);
                  mbar_init(smem_u32(&s_mbar[1]), 1); }
    __syncthreads();
    const uint32_t tmem = s_tmem;
    const uint32_t mba[2] = { smem_u32(&s_mbar[0]), smem_u32(&s_mbar[1]) };

    const int tileBase = blockIdx.x * TG;
    const int r    = t >> 1;
    const int half = t & 1;
    const __nv_bfloat16* fp = half ? g_fl : g_fh;
    const char* whp = (const char*)(g_Wh + whbase);
    const char* wlp = (const char*)(g_Wl + whbase);

    uint32_t ph[2]   = {0u, 0u};
    bool     pend[2] = {false, false};

    // nbr index of iteration it2 (row this thread gathers)
    auto nbr_of = [&](int it2) -> int {
        const int c = it2 / TG;
        const int j = it2 - c * TG;
        const int off = c / KCH;
        return g_nbr[off * NPTS + (tileBase + j) * BM + r];
    };
    // issue cp.async gather of iteration it2 into buffer b2
    auto issue_gather = [&](int it2, int b2, int nb) {
        const int c  = it2 / TG;
        const int off = c / KCH, kc = c - off * KCH;
        const char* src =
            (const char*)(fp + (size_t)(nb < 0 ? 0 : nb) * CIN + kc * 64);
        const uint32_t dst = aBase + b2 * ASTG + half * ATILE + r * 128;
        const int sz = nb >= 0 ? 16 : 0;
        #pragma unroll
        for (int s = 0; s < CSEG; ++s)
            cp16(dst + ((s ^ (r & 7)) << 4), src + s * 16, sz);
    };

    // prologue: gather(0) + nbr prefetch for 1
    int nbNext = nbr_of(0);
    issue_gather(0, 0, nbNext);
    cp_commit();
    nbNext = (TOT > 1) ? nbr_of(1) : 0;

    #pragma unroll 1
    for (int it = 0; it < TOT; ++it) {
        const int c    = it / TG;
        const int j    = it - c * TG;
        const int buf  = it & 1;
        const int nbuf = buf ^ 1;

        if (j == 0) {
            // drain all MMAs (they read old B), then refresh B via cp.async
            #pragma unroll
            for (int b = 0; b < 2; ++b)
                if (pend[b]) { mbar_wait(mba[b], ph[b]); ph[b] ^= 1;
                               pend[b] = false; }
            #pragma unroll
            for (int i = 0; i < BTILE / 16 / 256; ++i) {
                const int sg = (t + i * 256) << 4;
                cp16(bBase + sg,         whp + (size_t)c * BTILE + sg, 16);
                cp16(bBase + BTILE + sg, wlp + (size_t)c * BTILE + sg, 16);
            }
            cp_commit();
        } else if (pend[nbuf]) {
            // MMA(it-1) read nbuf; must finish before gather(it+1) overwrites
            mbar_wait(mba[nbuf], ph[nbuf]); ph[nbuf] ^= 1; pend[nbuf] = false;
        }

        if (it + 1 < TOT) {
            const int nbU = nbNext;
            if (it + 2 < TOT) nbNext = nbr_of(it + 2);
            issue_gather(it + 1, nbuf, nbU);
            cp_commit();
            cp_wait1();          // gather(it) [and B at boundary] complete
        } else {
            cp_wait0();
        }
        fence_proxy_async_sc();
        __syncthreads();

        if (wid == 0) {
            tc_fence_after();
            if (elect_one()) {
                const uint32_t ab = aBase + buf * ASTG;
                uint64_t dAh = mk_desc(ab);
                uint64_t dAl = mk_desc(ab + ATILE);
                uint64_t dBh = mk_desc(bBase);
                uint64_t dBl = mk_desc(bBase + BTILE);
                const uint32_t dTm = tmem + (uint32_t)(j * COUT);
                #pragma unroll
                for (int ks = 0; ks < NK; ++ks)
                    mma_ss_bf16(dTm, dAh + ks * 2, dBh + ks * 2, IDESC,
                                (c == 0 && ks == 0) ? 0u : 1u);
                #pragma unroll
                for (int ks = 0; ks < NK; ++ks)
                    mma_ss_bf16(dTm, dAh + ks * 2, dBl + ks * 2, IDESC, 1u);
                #pragma unroll
                for (int ks = 0; ks < NK; ++ks)
                    mma_ss_bf16(dTm, dAl + ks * 2, dBh + ks * 2, IDESC, 1u);
                tc_commit(mba[buf]);
            }
        }
        pend[buf] = true;
    }

    #pragma unroll
    for (int b = 0; b < 2; ++b)
        if (pend[b]) { mbar_wait(mba[b], ph[b]); ph[b] ^= 1; pend[b] = false; }
    tc_fence_after();

    // ---------------- epilogue ----------------
    const int grp     = wid >> 2;
    const int rw      = wid & 3;
    const int colBase = grp * CPW;

    for (int j = 0; j < TG; ++j) {
        const int tile = tileBase + j;
        const int row  = tile * BM + rw * 32 + lane;
        #pragma unroll
        for (int p = 0; p < CPW / 32; ++p) {
            uint32_t dr[32];
            ldtm_x32(dr, tmem + (uint32_t)(j * COUT + colBase + p * 32));
            tc_wait_ld();
            #pragma unroll
            for (int jj = 0; jj < 32; jj += 4) {
                float y[4];
                #pragma unroll
                for (int q = 0; q < 4; ++q) {
                    int col = colBase + p * 32 + jj + q;
                    y[q] = __uint_as_float(dr[jj + q]) + __ldg(bias + col);
                    float s = y[q], qq = y[q] * y[q];
                    #pragma unroll
                    for (int o = 16; o; o >>= 1) {
                        s  += __shfl_xor_sync(0xffffffffu, s, o);
                        qq += __shfl_xor_sync(0xffffffffu, qq, o);
                    }
                    if (lane == (col & 31)) {
                        sP[rw][col] = s;
                        sQ[rw][col] = qq;
                    }
                }
                *(float4*)(&g_conv[(size_t)row * COUT + colBase + p * 32 + jj]) =
                    make_float4(y[0], y[1], y[2], y[3]);
            }
        }
        __syncthreads();
        if (t < COUT) {
            g_part[(size_t)tile * COUT + t] =
                sP[0][t] + sP[1][t] + sP[2][t] + sP[3][t];
            g_partsq[(size_t)tile * COUT + t] =
                sQ[0][t] + sQ[1][t] + sQ[2][t] + sQ[3][t];
        }
        __syncthreads();
    }
    tc_fence_before();
    __syncthreads();
    if (wid == 0) tmem_dealloc(tmem, TG * COUT);

#else  // ------------------- scalar FFMA fallback -------------
    constexpr int TN   = COUT / 16;
    constexpr int SEGS = BK / 4;

    extern __shared__ __align__(16) float sm[];
    float* As = sm;
    float* Bs = sm + BK * BM;
    __shared__ int sN[BM];

    const int t  = threadIdx.x;
    const int tr = t >> 4;
    const int tc = t & 15;

    for (int tile = blockIdx.x * TG; tile < (blockIdx.x + 1) * TG; ++tile) {
        const int rowBase = tile * BM;

        unsigned long long acc[8][TN/2];
        #pragma unroll
        for (int i = 0; i < 8; i++)
            #pragma unroll
            for (int j = 0; j < TN/2; j++) acc[i][j] = 0ull;

        for (int k = 0; k < 27; k++) {
            __syncthreads();
            if (t < BM) sN[t] = g_nbr[k * NPTS + rowBase + t];
            __syncthreads();
            #pragma unroll
            for (int kc = 0; kc < KCH; kc++) {
                if (kc) __syncthreads();
                #pragma unroll
                for (int f = t; f < BM * SEGS; f += 256) {
                    int row = f / SEGS;
                    int seg = f - row * SEGS;
                    int nb  = sN[row];
                    float4 v = make_float4(0.f, 0.f, 0.f, 0.f);
                    if (nb >= 0)
                        v = *reinterpret_cast<const float4*>(
                            featF + (size_t)nb * CIN + kc * BK + seg * 4);
                    int rs = row ^ ((seg & 3) << 3);
                    As[(seg*4+0)*BM + rs] = v.x;
                    As[(seg*4+1)*BM + rs] = v.y;
                    As[(seg*4+2)*BM + rs] = v.z;
                    As[(seg*4+3)*BM + rs] = v.w;
                }
                const float4* Wk = (const float4*)(
                    g_Wf + wfbase + ((size_t)(k * KCH + kc)) * BK * COUT);
                #pragma unroll
                for (int f = t; f < BK * COUT / 4; f += 256)
                    reinterpret_cast<float4*>(Bs)[f] = Wk[f];
                __syncthreads();
                #pragma unroll 8
                for (int kk = 0; kk < BK; kk++) {
                    int rbase = (tr * 8) ^ (((kk >> 2) & 3) << 3);
                    float4 a0 = *reinterpret_cast<const float4*>(&As[kk*BM + rbase]);
                    float4 a1 = *reinterpret_cast<const float4*>(&As[kk*BM + rbase + 4]);
                    unsigned long long ad[8];
                    ad[0] = pack_dup(a0.x); ad[1] = pack_dup(a0.y);
                    ad[2] = pack_dup(a0.z); ad[3] = pack_dup(a0.w);
                    ad[4] = pack_dup(a1.x); ad[5] = pack_dup(a1.y);
                    ad[6] = pack_dup(a1.z); ad[7] = pack_dup(a1.w);
                    unsigned long long bb[TN/2];
                    const ulonglong2* bp = reinterpret_cast<const ulonglong2*>(
                        &Bs[kk * COUT + tc * TN]);
                    {
                        ulonglong2 b0 = bp[0];
                        bb[0] = b0.x; bb[1] = b0.y;
                        if constexpr (TN == 8) {
                            ulonglong2 b1 = bp[1];
                            bb[2] = b1.x; bb[3] = b1.y;
                        }
                    }
                    #pragma unroll
                    for (int i = 0; i < 8; i++)
                        #pragma unroll
                        for (int j = 0; j < TN/2; j++)
                            fma2(acc[i][j], ad[i], bb[j]);
                }
            }
        }

        float bv[TN];
        #pragma unroll
        for (int j = 0; j < TN; j++) bv[j] = bias[tc * TN + j];
        float cs[TN], cq[TN];
        #pragma unroll
        for (int j = 0; j < TN; j++) { cs[j] = 0.f; cq[j] = 0.f; }

        #pragma unroll
        for (int i = 0; i < 8; i++) {
            float yv[TN];
            #pragma unroll
            for (int j = 0; j < TN/2; j++) {
                float2 p = unpack2(acc[i][j]);
                yv[2*j]   = p.x + bv[2*j];
                yv[2*j+1] = p.y + bv[2*j+1];
            }
            #pragma unroll
            for (int j = 0; j < TN; j++) { cs[j] += yv[j]; cq[j] += yv[j]*yv[j]; }
            int row = rowBase + tr * 8 + i;
            #pragma unroll
            for (int j = 0; j < TN; j += 4) {
                float4 o = make_float4(yv[j], yv[j+1], yv[j+2], yv[j+3]);
                *reinterpret_cast<float4*>(
                    &g_conv[(size_t)row * COUT + tc * TN + j]) = o;
            }
        }

        __syncthreads();
        #pragma unroll
        for (int j = 0; j < TN; j++) As[tr * COUT + tc * TN + j] = cs[j];
        __syncthreads();
        if (t < COUT) {
            float s = 0.f;
            #pragma unroll
            for (int rr = 0; rr < 16; rr++) s += As[rr * COUT + t];
            g_part[(size_t)tile * COUT + t] = s;
        }
        __syncthreads();
        #pragma unroll
        for (int j = 0; j < TN; j++) As[tr * COUT + tc * TN + j] = cq[j];
        __syncthreads();
        if (t < COUT) {
            float s = 0.f;
            #pragma unroll
            for (int rr = 0; rr < 16; rr++) s += As[rr * COUT + t];
            g_partsq[(size_t)tile * COUT + t] = s;
        }
        __syncthreads();
    }
#endif
}

// ---------------- BN statistics ----------------
__global__ void bn_reduce_kernel(const float* __restrict__ gamma,
                                 const float* __restrict__ beta, int cout) {
    __shared__ float ss[256], sq[256];
    int c = blockIdx.x;
    int t = threadIdx.x;
    float s = 0.f, q = 0.f;
    for (int b = t; b < NBLK; b += 256) {
        s += g_part[b * cout + c];
        q += g_partsq[b * cout + c];
    }
    ss[t] = s; sq[t] = q;
    __syncthreads();
    for (int o = 128; o > 0; o >>= 1) {
        if (t < o) { ss[t] += ss[t + o]; sq[t] += sq[t + o]; }
        __syncthreads();
    }
    if (t == 0) {
        float mean = ss[0] * INVN;
        float var  = sq[0] * INVN - mean * mean;
        float sc   = gamma[c] * rsqrtf(var + BN_EPS);
        g_scale[c] = sc;
        g_shift[c] = beta[c] - mean * sc;
    }
}

// ---------------- BN apply + ReLU ----------------
template <int COUT>
__global__ void bnrelu_kernel() {
    int i = blockIdx.x * 256 + threadIdx.x;
    int c = i & (COUT - 1);
    float v = fmaf(g_conv[i], g_scale[c], g_shift[c]);
    v = v > 0.f ? v : 0.f;
#if !HAS_TCGEN05
    g_feat[i] = v;
#endif
    __nv_bfloat16 h = __float2bfloat16(v);
    g_fh[i] = h;
    g_fl[i] = __float2bfloat16(v - __bfloat162float(h));
}

// ---------------- final dense scatter ----------------
__global__ void final_out_kernel(float* __restrict__ out) {
    int idx = blockIdx.x * 256 + threadIdx.x;
    int lin = idx % VOLPB;
    int bc  = idx / VOLPB;
    int c = bc & 63;
    int b = bc >> 6;
    int row = g_map[b * VOLPB + lin];
    float v = 0.f;
    if (row >= 0) {
        float y = fmaf(g_conv[(size_t)row * 64 + c], g_scale[c], g_shift[c]);
        v = y > 0.f ? y : 0.f;
    }
    out[idx] = v;
}

// ---------------- launch ----------------
extern "C" void kernel_launch(void* const* d_in, const int* in_sizes, int n_in,
                              void* d_out, int out_size) {
    (void)in_sizes; (void)out_size;
    int base = (n_in >= 15) ? 3 : 2;
    const float* features = (const float*)d_in[0];
    const int*   indices  = (const int*)d_in[1];
    const float* W0  = (const float*)d_in[base + 0];
    const float* b0  = (const float*)d_in[base + 1];
    const float* ga0 = (const float*)d_in[base + 2];
    const float* be0 = (const float*)d_in[base + 3];
    const float* W1  = (const float*)d_in[base + 4];
    const float* b1  = (const float*)d_in[base + 5];
    const float* ga1 = (const float*)d_in[base + 6];
    const float* be1 = (const float*)d_in[base + 7];
    const float* W2  = (const float*)d_in[base + 8];
    const float* b2  = (const float*)d_in[base + 9];
    const float* ga2 = (const float*)d_in[base + 10];
    const float* be2 = (const float*)d_in[base + 11];
    float* out = (float*)d_out;

    float* featp = nullptr;
    cudaGetSymbolAddress((void**)&featp, g_feat);

    constexpr int SM64  = 4 * 16384 + 2 * 64  * 128 + 1024;  // 82944
    constexpr int SM128 = 4 * 16384 + 2 * 128 * 128 + 1024;  // 99328
    cudaFuncSetAttribute(conv_kernel<16, 64, 16, 1, 4>,
                         cudaFuncAttributeMaxDynamicSharedMemorySize, SM64);
    cudaFuncSetAttribute(conv_kernel<64, 128, 64, 1, 2>,
                         cudaFuncAttributeMaxDynamicSharedMemorySize, SM128);
    cudaFuncSetAttribute(conv_kernel<128, 64, 64, 2, 4>,
                         cudaFuncAttributeMaxDynamicSharedMemorySize, SM64);

    prep0_kernel<<<NVOX / 256, 256>>>(W0, W1, W2);
    prep1_kernel<<<NPTS * 16 / 256, 256>>>(indices, features);
    build_nbr_kernel<<<27 * NPTS / 256, 256>>>(indices);

    conv_kernel<16, 64, 16, 1, 4><<<NBLK / 4, 256, SM64>>>(features, b0,
                                                           WH0, WF0);
    bn_reduce_kernel<<<64, 256>>>(ga0, be0, 64);
    bnrelu_kernel<64><<<NPTS * 64 / 256, 256>>>();

    conv_kernel<64, 128, 64, 1, 2><<<NBLK / 2, 256, SM128>>>(featp, b1,
                                                             WH1, WF1);
    bn_reduce_kernel<<<128, 256>>>(ga1, be1, 128);
    bnrelu_kernel<128><<<NPTS * 128 / 256, 256>>>();

    conv_kernel<128, 64, 64, 2, 4><<<NBLK / 4, 256, SM64>>>(featp, b2,
                                                            WH2, WF2);
    bn_reduce_kernel<<<64, 256>>>(ga2, be2, 64);

    final_out_kernel<<<(BATCH * 64 * VOLPB) / 256, 256>>>(out);
}

// round 10
// speedup vs baseline: 3.3978x; 1.0406x over previous
#include <cuda_runtime.h>
#include <cuda_bf16.h>
#include <cstdint>

#define DD     12
#define VOLPB  1728
#define BATCH  512
#define NPTS   442368
#define NVOX   884736
#define BM     128
#define NBLK   3456
#define INVN   (1.0f/442368.0f)
#define BN_EPS 1e-5f

// packed bf16 weight regions (elements)
#define WH0 0
#define WH1 28672
#define WH2 249856
#define WHTOT 471040
// fp32 fallback weight regions
#define WF0 0
#define WF1 27648
#define WF2 248832
#define WFTOT 470016

#if defined(__CUDA_ARCH__) && (defined(__CUDA_ARCH_FEAT_SM103_ALL) || \
    defined(__CUDA_ARCH_FEAT_SM100_ALL) || defined(__CUDA_ARCH_FEAT_SM101_ALL))
#define HAS_TCGEN05 1
#else
#define HAS_TCGEN05 0
#endif

// ---------------- device scratch ----------------
__device__ __align__(256) int            g_map[NVOX];
__device__ __align__(256) int            g_nbr[27 * NPTS];
__device__ __align__(256) float          g_feat[(size_t)NPTS * 128];
__device__ __align__(256) __nv_bfloat16  g_fh[(size_t)NPTS * 128];
__device__ __align__(256) __nv_bfloat16  g_fl[(size_t)NPTS * 128];
__device__ __align__(256) float          g_conv[(size_t)NPTS * 128];
__device__ __align__(256) __nv_bfloat16  g_Wh[WHTOT];
__device__ __align__(256) __nv_bfloat16  g_Wl[WHTOT];
__device__ __align__(256) float          g_Wf[WFTOT];
__device__ __align__(256) float          g_part[NBLK * 128];
__device__ __align__(256) float          g_partsq[NBLK * 128];
__device__ __align__(256) float          g_scale[128];
__device__ __align__(256) float          g_shift[128];

// ---------------- generic helpers ----------------
__device__ __forceinline__ uint32_t smem_u32(const void* p) {
    uint32_t a;
    asm("{ .reg .u64 t; cvta.to.shared.u64 t, %1; cvt.u32.u64 %0, t; }"
        : "=r"(a) : "l"(p));
    return a;
}

#if HAS_TCGEN05
__device__ __forceinline__ bool elect_one() {
    uint32_t pred;
    asm volatile("{\n\t.reg .pred p;\n\telect.sync _|p, 0xFFFFFFFF;\n\t"
                 "selp.b32 %0, 1, 0, p;\n\t}" : "=r"(pred));
    return pred != 0;
}
__device__ __forceinline__ void mbar_init(uint32_t addr, uint32_t cnt) {
    asm volatile("mbarrier.init.shared.b64 [%0], %1;" :: "r"(addr), "r"(cnt)
                 : "memory");
}
__device__ __forceinline__ void mbar_wait(uint32_t addr, uint32_t phase) {
    asm volatile(
        "{\n\t.reg .pred P;\n\t"
        "W%=:\n\t"
        "mbarrier.try_wait.parity.acquire.cta.shared::cta.b64 P, [%0], %1, 0x989680;\n\t"
        "@!P bra W%=;\n\t}"
        :: "r"(addr), "r"(phase) : "memory");
}
__device__ __forceinline__ void tmem_alloc(uint32_t dst_smem, uint32_t ncols) {
    asm volatile("tcgen05.alloc.cta_group::1.sync.aligned.shared::cta.b32 [%0], %1;"
                 :: "r"(dst_smem), "r"(ncols) : "memory");
}
__device__ __forceinline__ void tmem_relinquish() {
    asm volatile("tcgen05.relinquish_alloc_permit.cta_group::1.sync.aligned;");
}
__device__ __forceinline__ void tmem_dealloc(uint32_t base, uint32_t ncols) {
    asm volatile("tcgen05.dealloc.cta_group::1.sync.aligned.b32 %0, %1;"
                 :: "r"(base), "r"(ncols));
}
__device__ __forceinline__ void fence_proxy_async_sc() {
    asm volatile("fence.proxy.async.shared::cta;" ::: "memory");
}
__device__ __forceinline__ void tc_fence_after() {
    asm volatile("tcgen05.fence::after_thread_sync;" ::: "memory");
}
__device__ __forceinline__ void tc_fence_before() {
    asm volatile("tcgen05.fence::before_thread_sync;" ::: "memory");
}
__device__ __forceinline__ void tc_wait_ld() {
    asm volatile("tcgen05.wait::ld.sync.aligned;" ::: "memory");
}
__device__ __forceinline__ void tc_commit(uint32_t mbar) {
    asm volatile(
        "tcgen05.commit.cta_group::1.mbarrier::arrive::one.shared::cluster.b64 [%0];"
        :: "r"(mbar) : "memory");
}
__device__ __forceinline__ void mma_ss_bf16(uint32_t d, uint64_t ad, uint64_t bd,
                                            uint32_t idesc, uint32_t en) {
    asm volatile(
        "{\n\t.reg .pred p;\n\tsetp.ne.u32 p, %4, 0;\n\t"
        "tcgen05.mma.cta_group::1.kind::f16 [%0], %1, %2, %3, {%5,%5,%5,%5}, p;\n\t}"
        :: "r"(d), "l"(ad), "l"(bd), "r"(idesc), "r"(en), "r"(0u) : "memory");
}
__device__ __forceinline__ void ldtm_x32(uint32_t* r, uint32_t addr) {
    asm volatile(
        "tcgen05.ld.sync.aligned.32x32b.x32.b32 "
        "{%0, %1, %2, %3, %4, %5, %6, %7, "
        " %8, %9, %10, %11, %12, %13, %14, %15, "
        " %16, %17, %18, %19, %20, %21, %22, %23, "
        " %24, %25, %26, %27, %28, %29, %30, %31}, [%32];"
        : "=r"(r[0]),  "=r"(r[1]),  "=r"(r[2]),  "=r"(r[3]),
          "=r"(r[4]),  "=r"(r[5]),  "=r"(r[6]),  "=r"(r[7]),
          "=r"(r[8]),  "=r"(r[9]),  "=r"(r[10]), "=r"(r[11]),
          "=r"(r[12]), "=r"(r[13]), "=r"(r[14]), "=r"(r[15]),
          "=r"(r[16]), "=r"(r[17]), "=r"(r[18]), "=r"(r[19]),
          "=r"(r[20]), "=r"(r[21]), "=r"(r[22]), "=r"(r[23]),
          "=r"(r[24]), "=r"(r[25]), "=r"(r[26]), "=r"(r[27]),
          "=r"(r[28]), "=r"(r[29]), "=r"(r[30]), "=r"(r[31])
        : "r"(addr));
}
__device__ __forceinline__ uint64_t mk_desc(uint32_t addr) {
    const uint64_t base = (2ull << 61) | (1ull << 46) | (64ull << 32) | (1ull << 16);
    return base | ((addr >> 4) & 0x3FFF);
}
__device__ __forceinline__ void cp16(uint32_t dst, const void* src, int srcsz) {
    asm volatile("cp.async.cg.shared.global [%0], [%1], 16, %2;"
                 :: "r"(dst), "l"(src), "r"(srcsz) : "memory");
}
__device__ __forceinline__ void cp_mbar_arrive(uint32_t mbar) {
    asm volatile("cp.async.mbarrier.arrive.noinc.shared.b64 [%0];"
                 :: "r"(mbar) : "memory");
}
#else
__device__ __forceinline__ unsigned long long pack_dup(float a) {
    unsigned long long r;
    asm("mov.b64 %0, {%1, %1};" : "=l"(r) : "f"(a));
    return r;
}
__device__ __forceinline__ void fma2(unsigned long long& acc,
                                     unsigned long long a,
                                     unsigned long long b) {
    asm("fma.rn.f32x2 %0, %1, %2, %0;" : "+l"(acc) : "l"(a), "l"(b));
}
__device__ __forceinline__ float2 unpack2(unsigned long long v) {
    float lo, hi;
    asm("mov.b64 {%0, %1}, %2;" : "=f"(lo), "=f"(hi) : "l"(v));
    return make_float2(lo, hi);
}
#endif

// ---------------- prep ----------------
#if !HAS_TCGEN05
template <int CIN, int COUT, int BK, int KCH>
__device__ __forceinline__ void wsplit_fb(const float* __restrict__ W, int idx,
                                          int wfbase) {
    int ci   = idx & 63;
    int rowI = idx >> 6;
    int co   = rowI % COUT;
    int c    = rowI / COUT;
    int off = c / KCH, kc = c % KCH;
    if (ci < BK)
        g_Wf[wfbase + ((size_t)c * BK + ci) * COUT + co] =
            W[((size_t)(off * CIN + kc * 64 + ci)) * COUT + co];
}
#endif

__global__ void prep0_kernel(const float* __restrict__ W0,
                             const float* __restrict__ W1,
                             const float* __restrict__ W2) {
    int i = blockIdx.x * 256 + threadIdx.x;
    if (i < NVOX) g_map[i] = -1;
#if HAS_TCGEN05
    // packed bf16 hi/lo layout, SW128 pre-swizzled, chunk-major
    float v = 0.f;
    int dst = -1;
    if (i < WH1) {                       // conv0 packed: 7 chunks x 64ci x 64co
        int ci64 = i & 63;
        int rowI = i >> 6;
        int co = rowI & 63;
        int c  = rowI >> 6;              // 0..6
        int p = ci64 >> 4, ci16 = ci64 & 15;
        int ko = c * 4 + p;
        if (ko < 27) v = W0[((size_t)(ko * 16 + ci16)) * 64 + co];
        dst = WH0 + rowI * 64 + ((((ci64 >> 3) ^ (co & 7)) << 3) | (ci64 & 7));
    } else if (i < WH2) {                // conv1: 27 chunks x 64ci x 128co
        int idx2 = i - WH1;
        int ci = idx2 & 63;
        int rowI = idx2 >> 6;
        int co = rowI & 127;
        int c  = rowI >> 7;
        v = W1[((size_t)(c * 64 + ci)) * 128 + co];
        dst = WH1 + rowI * 64 + ((((ci >> 3) ^ (co & 7)) << 3) | (ci & 7));
    } else if (i < WHTOT) {              // conv2: 54 chunks x 64ci x 64co
        int idx2 = i - WH2;
        int ci = idx2 & 63;
        int rowI = idx2 >> 6;
        int co = rowI & 63;
        int c  = rowI >> 6;              // 0..53
        int off = c >> 1, kc = c & 1;
        v = W2[((size_t)(off * 128 + kc * 64 + ci)) * 64 + co];
        dst = WH2 + rowI * 64 + ((((ci >> 3) ^ (co & 7)) << 3) | (ci & 7));
    }
    if (dst >= 0) {
        __nv_bfloat16 h = __float2bfloat16(v);
        g_Wh[dst] = h;
        g_Wl[dst] = __float2bfloat16(v - __bfloat162float(h));
    }
#else
    if (i < 27 * 64 * 64)            wsplit_fb<16, 64, 16, 1>(W0, i, WF0);
    else if (i < 27*64*64 + 27*64*128)
        wsplit_fb<64, 128, 64, 1>(W1, i - 27*64*64, WF1);
    else if (i < 27*64*64 + 27*64*128 + 54*64*64)
        wsplit_fb<128, 64, 64, 2>(W2, i - 27*64*64 - 27*64*128, WF2);
#endif
}

__global__ void prep1_kernel(const int* __restrict__ idxs,
                             const float* __restrict__ f) {
    int i = blockIdx.x * 256 + threadIdx.x;
    if (i < NPTS) {
        int b = idxs[4*i+0], z = idxs[4*i+1], y = idxs[4*i+2], x = idxs[4*i+3];
        g_map[((b*DD + z)*DD + y)*DD + x] = i;
    }
    float v = f[i];
    __nv_bfloat16 h = __float2bfloat16(v);
    g_fh[i] = h;
    g_fl[i] = __float2bfloat16(v - __bfloat162float(h));
}

__global__ void build_nbr_kernel(const int* __restrict__ idxs) {
    int tid = blockIdx.x * 256 + threadIdx.x;
    int k = tid / NPTS;
    int n = tid - k * NPTS;
    int b = idxs[4*n+0], z = idxs[4*n+1], y = idxs[4*n+2], x = idxs[4*n+3];
    int zz = z + k/9 - 1, yy = y + (k/3)%3 - 1, xx = x + (k%3) - 1;
    int r = -1;
    if ((unsigned)zz < DD && (unsigned)yy < DD && (unsigned)xx < DD)
        r = g_map[((b*DD + zz)*DD + yy)*DD + xx];
    g_nbr[tid] = r;
}

// ---------------- conv ----------------
// tcgen05: warp-specialized. warps 0-6 produce (cp.async), warp 7 MMAs.
// item i = (chunk c = i/TG, tile j = i%TG); K=64 per item.
template <int CIN, int COUT, int GOFF, int KCH, int TG, int NCH>
__global__ void __launch_bounds__(256)
conv_kernel(const float* __restrict__ featF,
            const float* __restrict__ bias,
            int whbase, int wfbase) {
#if HAS_TCGEN05
    constexpr int TOT    = NCH * TG;
    constexpr int NK     = 4;               // K=64 per item
    constexpr int SUBSEG = 8 / GOFF;        // 16B segs per offset per row
    constexpr int ATILE  = 128 * 128;
    constexpr int ASTG   = 2 * ATILE;       // hi+lo
    constexpr int BTILEB = COUT * 128;      // bytes per half
    constexpr int CPW    = COUT / 2;
    constexpr uint32_t IDESC =
        (1u << 4) | (1u << 7) | (1u << 10) | ((COUT / 8) << 17) | (8u << 24);

    extern __shared__ __align__(16) char dsm_raw[];
    __shared__ __align__(8) unsigned long long s_full[2], s_cmt[2];
    __shared__ uint32_t s_tmem;
    __shared__ float sP[4][128], sQ[4][128];

    char* smp = (char*)((((uintptr_t)dsm_raw) + 1023) & ~(uintptr_t)1023);
    const uint32_t smu   = smem_u32(smp);
    const uint32_t aBase = smu;
    const uint32_t bBase = smu + 2 * ASTG;

    const int t    = threadIdx.x;
    const int wid  = t >> 5;
    const int lane = t & 31;

    if (wid == 0) {
        tmem_alloc(smem_u32(&s_tmem), TG * COUT);
        tmem_relinquish();
    }
    if (t == 0) {
        mbar_init(smem_u32(&s_full[0]), 224);
        mbar_init(smem_u32(&s_full[1]), 224);
        mbar_init(smem_u32(&s_cmt[0]), 1);
        mbar_init(smem_u32(&s_cmt[1]), 1);
    }
    __syncthreads();
    const uint32_t tmem = s_tmem;
    const uint32_t fmb[2] = { smem_u32(&s_full[0]), smem_u32(&s_full[1]) };
    const uint32_t cmb[2] = { smem_u32(&s_cmt[0]),  smem_u32(&s_cmt[1])  };

    const int tileBase = blockIdx.x * TG;

    if (wid < 7) {
        // ======================= PRODUCERS =======================
        const char* whp = (const char*)(g_Wh + whbase);
        const char* wlp = (const char*)(g_Wl + whbase);
        uint32_t cph[2] = {0u, 0u};
        int      cws[2] = {0, 1};           // first commit on slot s is item s

        auto wait_until = [&](int slot, int target) {
            while (cws[slot] <= target) {
                mbar_wait(cmb[slot], cph[slot]);
                cph[slot] ^= 1;
                cws[slot] += 2;
            }
        };

        int nb[2][GOFF];
        auto prefetch = [&](int i) {
            const int c = i / TG, j = i - (i / TG) * TG;
            const int off = c / KCH;
            #pragma unroll
            for (int k = 0; k < 2; ++k) {
                int u = t + k * 224;
                if (u < 256) {
                    int row = u >> 1;
                    #pragma unroll
                    for (int p = 0; p < GOFF; ++p) {
                        int ko = off * GOFF + p;
                        nb[k][p] = (ko < 27)
                            ? g_nbr[ko * NPTS + (tileBase + j) * BM + row] : -1;
                    }
                }
            }
        };

        prefetch(0);
        #pragma unroll 1
        for (int i = 0; i < TOT; ++i) {
            const int c = i / TG, j = i - c * TG;
            const int s = i & 1;
            const int kc = c % KCH;

            wait_until(s, i - 2);
            if (j == 0) {
                if (c > 0) wait_until((i - 1) & 1, i - 1);
                // refresh B (single buffer; chunk c-1 MMAs all retired)
                for (int q = t; q < BTILEB / 16; q += 224) {
                    cp16(bBase + q * 16,
                         whp + (size_t)c * BTILEB + q * 16, 16);
                    cp16(bBase + BTILEB + q * 16,
                         wlp + (size_t)c * BTILEB + q * 16, 16);
                }
            }
            // A gathers
            #pragma unroll
            for (int k = 0; k < 2; ++k) {
                int u = t + k * 224;
                if (u < 256) {
                    const int row = u >> 1, half = u & 1;
                    const __nv_bfloat16* fp = half ? g_fl : g_fh;
                    const uint32_t dst =
                        aBase + s * ASTG + half * ATILE + row * 128;
                    #pragma unroll
                    for (int p = 0; p < GOFF; ++p) {
                        const int nbv = nb[k][p];
                        const char* src = (const char*)
                            (fp + (size_t)(nbv < 0 ? 0 : nbv) * CIN + kc * 64);
                        const int sz = nbv >= 0 ? 16 : 0;
                        #pragma unroll
                        for (int s2 = 0; s2 < SUBSEG; ++s2) {
                            int g = p * SUBSEG + s2;
                            cp16(dst + (((g ^ (row & 7)) << 4)),
                                 src + s2 * 16, sz);
                        }
                    }
                }
            }
            cp_mbar_arrive(fmb[s]);
            if (i + 1 < TOT) prefetch(i + 1);
        }
        // ensure all MMAs retired before epilogue
        wait_until(0, TOT - 1);
        wait_until(1, TOT - 1);
    } else {
        // ======================= CONSUMER (warp 7) =======================
        uint32_t fph[2] = {0u, 0u};
        #pragma unroll 1
        for (int i = 0; i < TOT; ++i) {
            const int c = i / TG, j = i - c * TG;
            const int s = i & 1;
            mbar_wait(fmb[s], fph[s]);
            fph[s] ^= 1;
            fence_proxy_async_sc();
            tc_fence_after();
            if (elect_one()) {
                const uint32_t ab = aBase + s * ASTG;
                uint64_t dAh = mk_desc(ab);
                uint64_t dAl = mk_desc(ab + ATILE);
                uint64_t dBh = mk_desc(bBase);
                uint64_t dBl = mk_desc(bBase + BTILEB);
                const uint32_t dTm = tmem + (uint32_t)(j * COUT);
                #pragma unroll
                for (int ks = 0; ks < NK; ++ks)
                    mma_ss_bf16(dTm, dAh + ks * 2, dBh + ks * 2, IDESC,
                                (c == 0 && ks == 0) ? 0u : 1u);
                #pragma unroll
                for (int ks = 0; ks < NK; ++ks)
                    mma_ss_bf16(dTm, dAh + ks * 2, dBl + ks * 2, IDESC, 1u);
                #pragma unroll
                for (int ks = 0; ks < NK; ++ks)
                    mma_ss_bf16(dTm, dAl + ks * 2, dBh + ks * 2, IDESC, 1u);
                tc_commit(cmb[s]);
            }
        }
    }

    __syncthreads();
    tc_fence_after();

    // ---------------- epilogue ----------------
    const int grp     = wid >> 2;
    const int rw      = wid & 3;
    const int colBase = grp * CPW;

    for (int j = 0; j < TG; ++j) {
        const int tile = tileBase + j;
        const int row  = tile * BM + rw * 32 + lane;
        #pragma unroll
        for (int p = 0; p < CPW / 32; ++p) {
            uint32_t dr[32];
            ldtm_x32(dr, tmem + (uint32_t)(j * COUT + colBase + p * 32));
            tc_wait_ld();
            #pragma unroll
            for (int jj = 0; jj < 32; jj += 4) {
                float y[4];
                #pragma unroll
                for (int q = 0; q < 4; ++q) {
                    int col = colBase + p * 32 + jj + q;
                    y[q] = __uint_as_float(dr[jj + q]) + __ldg(bias + col);
                    float s = y[q], qq = y[q] * y[q];
                    #pragma unroll
                    for (int o = 16; o; o >>= 1) {
                        s  += __shfl_xor_sync(0xffffffffu, s, o);
                        qq += __shfl_xor_sync(0xffffffffu, qq, o);
                    }
                    if (lane == (col & 31)) {
                        sP[rw][col] = s;
                        sQ[rw][col] = qq;
                    }
                }
                *(float4*)(&g_conv[(size_t)row * COUT + colBase + p * 32 + jj]) =
                    make_float4(y[0], y[1], y[2], y[3]);
            }
        }
        __syncthreads();
        if (t < COUT) {
            g_part[(size_t)tile * COUT + t] =
                sP[0][t] + sP[1][t] + sP[2][t] + sP[3][t];
            g_partsq[(size_t)tile * COUT + t] =
                sQ[0][t] + sQ[1][t] + sQ[2][t] + sQ[3][t];
        }
        __syncthreads();
    }
    tc_fence_before();
    __syncthreads();
    if (wid == 0) tmem_dealloc(tmem, TG * COUT);

#else  // ------------------- scalar FFMA fallback -------------
    constexpr int BK   = (CIN < 64) ? CIN : 64;
    constexpr int TN   = COUT / 16;
    constexpr int SEGS = BK / 4;

    extern __shared__ __align__(16) float sm[];
    float* As = sm;
    float* Bs = sm + BK * BM;
    __shared__ int sN[BM];

    const int t  = threadIdx.x;
    const int tr = t >> 4;
    const int tc = t & 15;

    for (int tile = blockIdx.x * TG; tile < (blockIdx.x + 1) * TG; ++tile) {
        const int rowBase = tile * BM;

        unsigned long long acc[8][TN/2];
        #pragma unroll
        for (int i = 0; i < 8; i++)
            #pragma unroll
            for (int j = 0; j < TN/2; j++) acc[i][j] = 0ull;

        for (int k = 0; k < 27; k++) {
            __syncthreads();
            if (t < BM) sN[t] = g_nbr[k * NPTS + rowBase + t];
            __syncthreads();
            #pragma unroll
            for (int kc = 0; kc < KCH; kc++) {
                if (kc) __syncthreads();
                #pragma unroll
                for (int f = t; f < BM * SEGS; f += 256) {
                    int row = f / SEGS;
                    int seg = f - row * SEGS;
                    int nb  = sN[row];
                    float4 v = make_float4(0.f, 0.f, 0.f, 0.f);
                    if (nb >= 0)
                        v = *reinterpret_cast<const float4*>(
                            featF + (size_t)nb * CIN + kc * BK + seg * 4);
                    int rs = row ^ ((seg & 3) << 3);
                    As[(seg*4+0)*BM + rs] = v.x;
                    As[(seg*4+1)*BM + rs] = v.y;
                    As[(seg*4+2)*BM + rs] = v.z;
                    As[(seg*4+3)*BM + rs] = v.w;
                }
                const float4* Wk = (const float4*)(
                    g_Wf + wfbase + ((size_t)(k * KCH + kc)) * BK * COUT);
                #pragma unroll
                for (int f = t; f < BK * COUT / 4; f += 256)
                    reinterpret_cast<float4*>(Bs)[f] = Wk[f];
                __syncthreads();
                #pragma unroll 8
                for (int kk = 0; kk < BK; kk++) {
                    int rbase = (tr * 8) ^ (((kk >> 2) & 3) << 3);
                    float4 a0 = *reinterpret_cast<const float4*>(&As[kk*BM + rbase]);
                    float4 a1 = *reinterpret_cast<const float4*>(&As[kk*BM + rbase + 4]);
                    unsigned long long ad[8];
                    ad[0] = pack_dup(a0.x); ad[1] = pack_dup(a0.y);
                    ad[2] = pack_dup(a0.z); ad[3] = pack_dup(a0.w);
                    ad[4] = pack_dup(a1.x); ad[5] = pack_dup(a1.y);
                    ad[6] = pack_dup(a1.z); ad[7] = pack_dup(a1.w);
                    unsigned long long bb[TN/2];
                    const ulonglong2* bp = reinterpret_cast<const ulonglong2*>(
                        &Bs[kk * COUT + tc * TN]);
                    {
                        ulonglong2 b0 = bp[0];
                        bb[0] = b0.x; bb[1] = b0.y;
                        if constexpr (TN == 8) {
                            ulonglong2 b1 = bp[1];
                            bb[2] = b1.x; bb[3] = b1.y;
                        }
                    }
                    #pragma unroll
                    for (int i = 0; i < 8; i++)
                        #pragma unroll
                        for (int j = 0; j < TN/2; j++)
                            fma2(acc[i][j], ad[i], bb[j]);
                }
            }
        }

        float bv[TN];
        #pragma unroll
        for (int j = 0; j < TN; j++) bv[j] = bias[tc * TN + j];
        float cs[TN], cq[TN];
        #pragma unroll
        for (int j = 0; j < TN; j++) { cs[j] = 0.f; cq[j] = 0.f; }

        #pragma unroll
        for (int i = 0; i < 8; i++) {
            float yv[TN];
            #pragma unroll
            for (int j = 0; j < TN/2; j++) {
                float2 p = unpack2(acc[i][j]);
                yv[2*j]   = p.x + bv[2*j];
                yv[2*j+1] = p.y + bv[2*j+1];
            }
            #pragma unroll
            for (int j = 0; j < TN; j++) { cs[j] += yv[j]; cq[j] += yv[j]*yv[j]; }
            int row = rowBase + tr * 8 + i;
            #pragma unroll
            for (int j = 0; j < TN; j += 4) {
                float4 o = make_float4(yv[j], yv[j+1], yv[j+2], yv[j+3]);
                *reinterpret_cast<float4*>(
                    &g_conv[(size_t)row * COUT + tc * TN + j]) = o;
            }
        }

        __syncthreads();
        #pragma unroll
        for (int j = 0; j < TN; j++) As[tr * COUT + tc * TN + j] = cs[j];
        __syncthreads();
        if (t < COUT) {
            float s = 0.f;
            #pragma unroll
            for (int rr = 0; rr < 16; rr++) s += As[rr * COUT + t];
            g_part[(size_t)tile * COUT + t] = s;
        }
        __syncthreads();
        #pragma unroll
        for (int j = 0; j < TN; j++) As[tr * COUT + tc * TN + j] = cq[j];
        __syncthreads();
        if (t < COUT) {
            float s = 0.f;
            #pragma unroll
            for (int rr = 0; rr < 16; rr++) s += As[rr * COUT + t];
            g_partsq[(size_t)tile * COUT + t] = s;
        }
        __syncthreads();
    }
#endif
}

// ---------------- BN statistics ----------------
__global__ void bn_reduce_kernel(const float* __restrict__ gamma,
                                 const float* __restrict__ beta, int cout) {
    __shared__ float ss[256], sq[256];
    int c = blockIdx.x;
    int t = threadIdx.x;
    float s = 0.f, q = 0.f;
    for (int b = t; b < NBLK; b += 256) {
        s += g_part[b * cout + c];
        q += g_partsq[b * cout + c];
    }
    ss[t] = s; sq[t] = q;
    __syncthreads();
    for (int o = 128; o > 0; o >>= 1) {
        if (t < o) { ss[t] += ss[t + o]; sq[t] += sq[t + o]; }
        __syncthreads();
    }
    if (t == 0) {
        float mean = ss[0] * INVN;
        float var  = sq[0] * INVN - mean * mean;
        float sc   = gamma[c] * rsqrtf(var + BN_EPS);
        g_scale[c] = sc;
        g_shift[c] = beta[c] - mean * sc;
    }
}

// ---------------- BN apply + ReLU ----------------
template <int COUT>
__global__ void bnrelu_kernel() {
    int i = blockIdx.x * 256 + threadIdx.x;
    int c = i & (COUT - 1);
    float v = fmaf(g_conv[i], g_scale[c], g_shift[c]);
    v = v > 0.f ? v : 0.f;
#if !HAS_TCGEN05
    g_feat[i] = v;
#endif
    __nv_bfloat16 h = __float2bfloat16(v);
    g_fh[i] = h;
    g_fl[i] = __float2bfloat16(v - __bfloat162float(h));
}

// ---------------- final dense scatter ----------------
__global__ void final_out_kernel(float* __restrict__ out) {
    int idx = blockIdx.x * 256 + threadIdx.x;
    int lin = idx % VOLPB;
    int bc  = idx / VOLPB;
    int c = bc & 63;
    int b = bc >> 6;
    int row = g_map[b * VOLPB + lin];
    float v = 0.f;
    if (row >= 0) {
        float y = fmaf(g_conv[(size_t)row * 64 + c], g_scale[c], g_shift[c]);
        v = y > 0.f ? y : 0.f;
    }
    out[idx] = v;
}

// ---------------- launch ----------------
extern "C" void kernel_launch(void* const* d_in, const int* in_sizes, int n_in,
                              void* d_out, int out_size) {
    (void)in_sizes; (void)out_size;
    int base = (n_in >= 15) ? 3 : 2;
    const float* features = (const float*)d_in[0];
    const int*   indices  = (const int*)d_in[1];
    const float* W0  = (const float*)d_in[base + 0];
    const float* b0  = (const float*)d_in[base + 1];
    const float* ga0 = (const float*)d_in[base + 2];
    const float* be0 = (const float*)d_in[base + 3];
    const float* W1  = (const float*)d_in[base + 4];
    const float* b1  = (const float*)d_in[base + 5];
    const float* ga1 = (const float*)d_in[base + 6];
    const float* be1 = (const float*)d_in[base + 7];
    const float* W2  = (const float*)d_in[base + 8];
    const float* b2  = (const float*)d_in[base + 9];
    const float* ga2 = (const float*)d_in[base + 10];
    const float* be2 = (const float*)d_in[base + 11];
    float* out = (float*)d_out;

    float* featp = nullptr;
    cudaGetSymbolAddress((void**)&featp, g_feat);

    constexpr int SM64  = 4 * 16384 + 2 * 64  * 128 + 1024;  // 82944
    constexpr int SM128 = 4 * 16384 + 2 * 128 * 128 + 1024;  // 99328
    cudaFuncSetAttribute(conv_kernel<16, 64, 4, 1, 4, 7>,
                         cudaFuncAttributeMaxDynamicSharedMemorySize, SM64);
    cudaFuncSetAttribute(conv_kernel<64, 128, 1, 1, 2, 27>,
                         cudaFuncAttributeMaxDynamicSharedMemorySize, SM128);
    cudaFuncSetAttribute(conv_kernel<128, 64, 1, 2, 4, 54>,
                         cudaFuncAttributeMaxDynamicSharedMemorySize, SM64);

    prep0_kernel<<<NVOX / 256, 256>>>(W0, W1, W2);
    prep1_kernel<<<NPTS * 16 / 256, 256>>>(indices, features);
    build_nbr_kernel<<<27 * NPTS / 256, 256>>>(indices);

    conv_kernel<16, 64, 4, 1, 4, 7><<<NBLK / 4, 256, SM64>>>(features, b0,
                                                             WH0, WF0);
    bn_reduce_kernel<<<64, 256>>>(ga0, be0, 64);
    bnrelu_kernel<64><<<NPTS * 64 / 256, 256>>>();

    conv_kernel<64, 128, 1, 1, 2, 27><<<NBLK / 2, 256, SM128>>>(featp, b1,
                                                                WH1, WF1);
    bn_reduce_kernel<<<128, 256>>>(ga1, be1, 128);
    bnrelu_kernel<128><<<NPTS * 128 / 256, 256>>>();

    conv_kernel<128, 64, 1, 2, 4, 54><<<NBLK / 4, 256, SM64>>>(featp, b2,
                                                               WH2, WF2);
    bn_reduce_kernel<<<64, 256>>>(ga2, be2, 64);

    final_out_kernel<<<(BATCH * 64 * VOLPB) / 256, 256>>>(out);
}